// round 8
// baseline (speedup 1.0000x reference)
#include <cuda_runtime.h>
#include <cuda_bf16.h>
#include <cstdint>

#define BSZ 2
#define SEQLEN 2048
#define NHEADS 32
#define HDIM 128
#define DIM 4096
#define NTOK (BSZ * SEQLEN)              // 4096
#define OUT_ELEMS ((size_t)NTOK * DIM)   // 16,777,216
#define WSZ ((size_t)DIM * DIM)

// ---------------- int8 GEMM tiling: 128x128 CTA, BK=32, 8-stage bulk ---------
#define CHUNKS 128                       // 4096 / 32
#define I8_TILE 4096                     // 128 rows x 32 B per digit per chunk
#define I8_STAGE 16384                   // Ah, Al, Bh, Bl
#define I8_NSTAGE 8
#define I8_SMEM (I8_NSTAGE * I8_STAGE + 64)   // 131136

// ---------------- attention tiling (unchanged) ----------------
#define AQ_STRIDE 272
#define AV_STRIDE 144
#define Q_BYTES (128 * AQ_STRIDE)
#define K_BYTES (64 * AQ_STRIDE)
#define VT_BYTES (128 * AV_STRIDE)
#define KVBUF_BYTES (2 * K_BYTES + 2 * VT_BYTES)
#define ATTN_SMEM (2 * Q_BYTES + 2 * KVBUF_BYTES)  // 212992

// ---------------- scratch (device globals; no allocation allowed) -----------
__device__ __align__(256) float g_Q[OUT_ELEMS];
__device__ __align__(256) float g_attn[OUT_ELEMS];
__device__ __align__(256) int8_t g_a8h[OUT_ELEMS];      // x digits, later attn
__device__ __align__(256) int8_t g_a8l[OUT_ELEMS];
__device__ __align__(256) int8_t g_w8h[4ull * WSZ];
__device__ __align__(256) int8_t g_w8l[4ull * WSZ];
__device__ __align__(256) float g_sX[NTOK];             // x row scales, later attn
__device__ __align__(256) float g_sW[4 * DIM];          // weight row scales
__device__ __align__(256) __nv_bfloat16 g_qh[OUT_ELEMS];
__device__ __align__(256) __nv_bfloat16 g_ql[OUT_ELEMS];
__device__ __align__(256) __nv_bfloat16 g_kh[OUT_ELEMS];
__device__ __align__(256) __nv_bfloat16 g_kl[OUT_ELEMS];
__device__ __align__(256) __nv_bfloat16 g_vth[OUT_ELEMS];
__device__ __align__(256) __nv_bfloat16 g_vtl[OUT_ELEMS];

// ---------------- PTX helpers ------------------------------------------------
__device__ __forceinline__ uint32_t smem_u32(const void* p) {
    uint32_t a;
    asm("{ .reg .u64 t; cvta.to.shared.u64 t, %1; cvt.u32.u64 %0, t; }" : "=r"(a) : "l"(p));
    return a;
}
__device__ __forceinline__ void cp16(uint32_t dst, const void* src) {
    asm volatile("cp.async.cg.shared.global [%0], [%1], 16;" :: "r"(dst), "l"(src));
}
__device__ __forceinline__ void bulk_cp(uint32_t dst, const void* src, uint32_t bytes,
                                        uint32_t mbar) {
    asm volatile(
        "cp.async.bulk.shared::cta.global.mbarrier::complete_tx::bytes [%0], [%1], %2, [%3];"
        :: "r"(dst), "l"(src), "r"(bytes), "r"(mbar) : "memory");
}
__device__ __forceinline__ void mbar_expect(uint32_t mbar, uint32_t bytes) {
    asm volatile("mbarrier.arrive.expect_tx.shared.b64 _, [%0], %1;"
                 :: "r"(mbar), "r"(bytes) : "memory");
}
__device__ __forceinline__ void mbar_wait(uint32_t mbar, uint32_t parity) {
    asm volatile(
        "{\n\t.reg .pred P;\n\t"
        "LAB%=:\n\t"
        "mbarrier.try_wait.parity.acquire.cta.shared::cta.b64 P, [%0], %1, 0x989680;\n\t"
        "@!P bra LAB%=;\n\t}"
        :: "r"(mbar), "r"(parity) : "memory");
}
__device__ __forceinline__ void ldsm4(uint32_t* r, uint32_t addr) {
    asm volatile("ldmatrix.sync.aligned.m8n8.x4.shared.b16 {%0,%1,%2,%3}, [%4];"
        : "=r"(r[0]), "=r"(r[1]), "=r"(r[2]), "=r"(r[3]) : "r"(addr));
}
__device__ __forceinline__ void mma16816(float* c, const uint32_t* a, const uint32_t* b) {
    asm volatile("mma.sync.aligned.m16n8k16.row.col.f32.bf16.bf16.f32 "
        "{%0,%1,%2,%3}, {%4,%5,%6,%7}, {%8,%9}, {%0,%1,%2,%3};"
        : "+f"(c[0]), "+f"(c[1]), "+f"(c[2]), "+f"(c[3])
        : "r"(a[0]), "r"(a[1]), "r"(a[2]), "r"(a[3]), "r"(b[0]), "r"(b[1]));
}
__device__ __forceinline__ void mma_s8(int* c, const uint32_t* a, const uint32_t* b) {
    asm volatile("mma.sync.aligned.m16n8k32.row.col.s32.s8.s8.s32 "
        "{%0,%1,%2,%3}, {%4,%5,%6,%7}, {%8,%9}, {%0,%1,%2,%3};"
        : "+r"(c[0]), "+r"(c[1]), "+r"(c[2]), "+r"(c[3])
        : "r"(a[0]), "r"(a[1]), "r"(a[2]), "r"(a[3]), "r"(b[0]), "r"(b[1]));
}
__device__ __forceinline__ void split2(float a, float b, uint32_t& hi, uint32_t& lo) {
    __nv_bfloat162 h = __floats2bfloat162_rn(a, b);
    float ra = a - __bfloat162float(h.x);
    float rb = b - __bfloat162float(h.y);
    __nv_bfloat162 l = __floats2bfloat162_rn(ra, rb);
    hi = *(uint32_t*)&h;
    lo = *(uint32_t*)&l;
}

// ---------------------------------------------------------------------------
// Per-row int8 2-digit quantization into the tiled+swizzled GEMM layout.
// Row r (4096 floats): scale = rowmax/16256; v = rint(x/scale); v = 128h + l.
// Tile (rt, ck) per digit: 128 rows x 32B at ((rt*128+ck)*128 + rr)*32,
// 16B halves XOR-swizzled by (rr>>2)&1.
// ---------------------------------------------------------------------------
__global__ __launch_bounds__(128) void quant_rows(const float* __restrict__ src,
                                                  int8_t* __restrict__ h8,
                                                  int8_t* __restrict__ l8,
                                                  float* __restrict__ scale) {
    __shared__ float red[4];
    int r = blockIdx.x, t = threadIdx.x;
    const float4* row = (const float4*)(src + (size_t)r * DIM);
    float4 v[8];
    float mx = 0.f;
#pragma unroll
    for (int i = 0; i < 8; i++) {
        v[i] = row[t + i * 128];
        mx = fmaxf(mx, fmaxf(fmaxf(fabsf(v[i].x), fabsf(v[i].y)),
                             fmaxf(fabsf(v[i].z), fabsf(v[i].w))));
    }
#pragma unroll
    for (int s = 16; s; s >>= 1) mx = fmaxf(mx, __shfl_xor_sync(0xffffffffu, mx, s));
    if ((t & 31) == 0) red[t >> 5] = mx;
    __syncthreads();
    mx = fmaxf(fmaxf(red[0], red[1]), fmaxf(red[2], red[3]));
    mx = fmaxf(mx, 1e-30f);
    float inv = 16256.f / mx;
    if (t == 0) scale[r] = mx / 16256.f;

    int rt = r >> 7, rr = r & 127;
    uint32_t sw = ((rr >> 2) & 1) << 4;
#pragma unroll
    for (int i = 0; i < 8; i++) {
        int k = (t + i * 128) * 4;
        float f[4] = {v[i].x, v[i].y, v[i].z, v[i].w};
        uint32_t hp = 0, lp = 0;
#pragma unroll
        for (int j = 0; j < 4; j++) {
            int vi = __float2int_rn(f[j] * inv);
            int h = ((vi + 16448) >> 7) - 128;
            int l = vi - (h << 7);
            hp |= (uint32_t)(h & 255) << (j * 8);
            lp |= (uint32_t)(l & 255) << (j * 8);
        }
        int ck = k >> 5, c = k & 31;
        size_t off = ((((size_t)(rt * 128 + ck)) * 128 + rr) << 5) +
                     ((((uint32_t)(c >> 4)) << 4) ^ sw) + (c & 15);
        *(uint32_t*)(h8 + off) = hp;
        *(uint32_t*)(l8 + off) = lp;
    }
}

// ---------------------------------------------------------------------------
// Int8 2-digit GEMM: C = sA[row]*sB[col]*(16384*Ah.Bh + 128*(Ah.Bl + Al.Bh)).
// CTA 128x128, BK=32, 8 warps of 64x32, 8-stage cp.async.bulk pipeline.
// Output routed to C0/C1/C2 by nt>>5 (fused QKV).
// ---------------------------------------------------------------------------
__global__ __launch_bounds__(256)
void gemm_i8(const int8_t* __restrict__ Ah, const int8_t* __restrict__ Al,
             const int8_t* __restrict__ Bh, const int8_t* __restrict__ Bl,
             const float* __restrict__ sA, const float* __restrict__ sB,
             float* __restrict__ C0, float* __restrict__ C1, float* __restrict__ C2) {
    extern __shared__ char sm_raw[];
    const uint32_t base = smem_u32(sm_raw);
    const uint32_t mb = base + I8_NSTAGE * I8_STAGE;
    const int tid = threadIdx.x;
    const int warp = tid >> 5, lane = tid & 31;
    const int wm = warp & 1, wn = warp >> 1;     // warp tile 64 x 32
    const int nt = blockIdx.x, mt = blockIdx.y;
    const size_t mtC = (size_t)mt * CHUNKS;
    const size_t ntC = (size_t)nt * CHUNKS;

    if (tid == 0) {
#pragma unroll
        for (int s = 0; s < I8_NSTAGE; s++)
            asm volatile("mbarrier.init.shared.b64 [%0], %1;" :: "r"(mb + 8 * s), "r"(1u) : "memory");
        asm volatile("fence.proxy.async.shared::cta;" ::: "memory");
    }
    __syncthreads();

#define I8ISSUE(c, s)                                                             \
    do {                                                                          \
        if (tid == 0) {                                                           \
            uint32_t mb_ = mb + 8 * (s);                                          \
            mbar_expect(mb_, I8_STAGE);                                           \
            uint32_t st_ = base + (s) * I8_STAGE;                                 \
            bulk_cp(st_,         (const char*)Ah + (mtC + (c)) * I8_TILE, I8_TILE, mb_); \
            bulk_cp(st_ + 4096,  (const char*)Al + (mtC + (c)) * I8_TILE, I8_TILE, mb_); \
            bulk_cp(st_ + 8192,  (const char*)Bh + (ntC + (c)) * I8_TILE, I8_TILE, mb_); \
            bulk_cp(st_ + 12288, (const char*)Bl + (ntC + (c)) * I8_TILE, I8_TILE, mb_); \
        }                                                                         \
    } while (0)

#pragma unroll
    for (int p = 0; p < I8_NSTAGE - 1; p++) I8ISSUE(p, p);

    // per-thread ldsm address offsets (within a 4KB digit plane)
    const int lr = lane & 15;
    const uint32_t c16h = (uint32_t)(lane >> 4) << 4;
    uint32_t aoff[4], boff[2];
#pragma unroll
    for (int mi = 0; mi < 4; mi++) {
        int rA = wm * 64 + mi * 16 + lr;
        aoff[mi] = (uint32_t)rA * 32 + (c16h ^ ((((uint32_t)rA >> 2) & 1) << 4));
    }
#pragma unroll
    for (int g = 0; g < 2; g++) {
        int rB = wn * 32 + g * 16 + lr;
        boff[g] = (uint32_t)rB * 32 + (c16h ^ ((((uint32_t)rB >> 2) & 1) << 4));
    }

    int hh[4][4][4], cr[4][4][4];
#pragma unroll
    for (int mi = 0; mi < 4; mi++)
#pragma unroll
        for (int ni = 0; ni < 4; ni++)
#pragma unroll
            for (int j = 0; j < 4; j++) { hh[mi][ni][j] = 0; cr[mi][ni][j] = 0; }

    for (int ck = 0; ck < CHUNKS; ck++) {
        const int s = ck & 7;
        mbar_wait(mb + 8 * s, (ck >> 3) & 1);
        const uint32_t sb = base + s * I8_STAGE;

        uint32_t bhf[2][4], blf[2][4];
#pragma unroll
        for (int g = 0; g < 2; g++) {
            ldsm4(bhf[g], sb + 8192 + boff[g]);
            ldsm4(blf[g], sb + 12288 + boff[g]);
        }
#pragma unroll
        for (int mi = 0; mi < 4; mi++) {
            uint32_t ahf[4], alf[4];
            ldsm4(ahf, sb + aoff[mi]);
            ldsm4(alf, sb + 4096 + aoff[mi]);
#pragma unroll
            for (int ni = 0; ni < 4; ni++) {
                const int g = ni >> 1, p = ni & 1;
                uint32_t bh2[2] = {bhf[g][p], bhf[g][p + 2]};
                uint32_t bl2[2] = {blf[g][p], blf[g][p + 2]};
                mma_s8(hh[mi][ni], ahf, bh2);
                mma_s8(cr[mi][ni], ahf, bl2);
                mma_s8(cr[mi][ni], alf, bh2);
            }
        }
        __syncthreads();
        if (ck + I8_NSTAGE - 1 < CHUNKS) I8ISSUE(ck + I8_NSTAGE - 1, (ck + I8_NSTAGE - 1) & 7);
    }

    // epilogue: fold digits with fp32 scales, route by nt>>5
    float* Cb = (nt < 32) ? C0 : (nt < 64) ? C1 : C2;
    const int rowb = mt * 128 + wm * 64 + (lane >> 2);
    const int colb = wn * 32 + (lane & 3) * 2;
#pragma unroll
    for (int mi = 0; mi < 4; mi++) {
        float sa0 = __ldg(sA + rowb + mi * 16);
        float sa1 = __ldg(sA + rowb + mi * 16 + 8);
#pragma unroll
        for (int ni = 0; ni < 4; ni++) {
            int colg = nt * 128 + colb + ni * 8;
            float sb0 = __ldg(sB + colg);
            float sb1 = __ldg(sB + colg + 1);
            float v0 = sa0 * sb0 * (16384.f * (float)hh[mi][ni][0] + 128.f * (float)cr[mi][ni][0]);
            float v1 = sa0 * sb1 * (16384.f * (float)hh[mi][ni][1] + 128.f * (float)cr[mi][ni][1]);
            float v2 = sa1 * sb0 * (16384.f * (float)hh[mi][ni][2] + 128.f * (float)cr[mi][ni][2]);
            float v3 = sa1 * sb1 * (16384.f * (float)hh[mi][ni][3] + 128.f * (float)cr[mi][ni][3]);
            float* p0 = Cb + (size_t)(rowb + mi * 16) * DIM + (nt & 31) * 128 + colb + ni * 8;
            float2 a = {v0, v1}, b2 = {v2, v3};
            *(float2*)p0 = a;
            *(float2*)(p0 + 8 * DIM) = b2;
        }
    }
}

// ---------------------------------------------------------------------------
// Rotary + bf16 split for Q (scaled by log2e/sqrt(d)) and K. (unchanged)
// ---------------------------------------------------------------------------
__global__ __launch_bounds__(256) void rotary_convert(
        const float* __restrict__ Q, float* __restrict__ Kf,
        const float* __restrict__ fc,
        __nv_bfloat16* __restrict__ qh, __nv_bfloat16* __restrict__ ql,
        __nv_bfloat16* __restrict__ kh, __nv_bfloat16* __restrict__ kl) {
    const float QSC = 1.44269504088896f / 11.3137084989848f;
    int idx = blockIdx.x * blockDim.x + threadIdx.x;
    int p = idx & 63;
    int h = (idx >> 6) & 31;
    int s = (idx >> 11) & (SEQLEN - 1);
    int b = idx >> 22;

    float c = fc[(s * 64 + p) * 2];
    float sn = fc[(s * 64 + p) * 2 + 1];

    size_t in = (((size_t)(b * SEQLEN + s) * NHEADS) + h) * HDIM + p * 2;
    size_t out = (((size_t)(b * NHEADS + h) * SEQLEN) + s) * HDIM + p * 2;

    float2 q = *(float2*)(Q + in);
    float2 k = *(float2*)(Kf + in);
    float2 qo = {q.x * c - q.y * sn, q.x * sn + q.y * c};
    float2 ko = {k.x * c - k.y * sn, k.x * sn + k.y * c};
    *(float2*)(Kf + in) = ko;

    uint32_t hi, lo;
    split2(qo.x * QSC, qo.y * QSC, hi, lo);
    *(uint32_t*)(qh + out) = hi;
    *(uint32_t*)(ql + out) = lo;
    split2(ko.x, ko.y, hi, lo);
    *(uint32_t*)(kh + out) = hi;
    *(uint32_t*)(kl + out) = lo;
}

// ---------------------------------------------------------------------------
// V transpose + split (unchanged)
// ---------------------------------------------------------------------------
__global__ __launch_bounds__(256) void v_transpose(const float* __restrict__ V,
                                                   __nv_bfloat16* __restrict__ vth,
                                                   __nv_bfloat16* __restrict__ vtl) {
    __shared__ float t[32][33];
    int s0 = blockIdx.x * 32, d0 = blockIdx.y * 32;
    int bh = blockIdx.z;
    int b = bh >> 5, h = bh & 31;
#pragma unroll
    for (int i = 0; i < 4; i++) {
        int s = s0 + threadIdx.y + i * 8;
        t[threadIdx.y + i * 8][threadIdx.x] =
            V[(((size_t)(b * SEQLEN + s) * NHEADS) + h) * HDIM + d0 + threadIdx.x];
    }
    __syncthreads();
#pragma unroll
    for (int i = 0; i < 4; i++) {
        int d = d0 + threadIdx.y + i * 8;
        float v = t[threadIdx.x][threadIdx.y + i * 8];
        __nv_bfloat16 hb = __float2bfloat16(v);
        size_t o = ((size_t)bh * HDIM + d) * SEQLEN + s0 + threadIdx.x;
        vth[o] = hb;
        vtl[o] = __float2bfloat16(v - __bfloat162float(hb));
    }
}

// ---------------------------------------------------------------------------
// Flash attention, split-bf16 mma.sync; epilogue writes fp32 [token][dim].
// ---------------------------------------------------------------------------
__global__ __launch_bounds__(256)
void flash_attn(const __nv_bfloat16* __restrict__ Qh, const __nv_bfloat16* __restrict__ Ql,
                const __nv_bfloat16* __restrict__ Kbh, const __nv_bfloat16* __restrict__ Kbl,
                const __nv_bfloat16* __restrict__ Vth, const __nv_bfloat16* __restrict__ Vtl,
                float* __restrict__ O) {
    extern __shared__ char sm_raw[];
    const uint32_t base = smem_u32(sm_raw);
    const int tid = threadIdx.x, warp = tid >> 5, lane = tid & 31;
    const int qt = blockIdx.x, h = blockIdx.y, b = blockIdx.z;
    const size_t bhd = (size_t)(b * NHEADS + h);

    const uint32_t sQh = base, sQl = base + Q_BYTES;
    const uint32_t sKV = base + 2 * Q_BYTES;

    {
        const char* gq = (const char*)(Qh + (bhd * SEQLEN + qt * 128) * HDIM);
        const char* gl = (const char*)(Ql + (bhd * SEQLEN + qt * 128) * HDIM);
        int row = tid >> 4, ch = tid & 15;
#pragma unroll
        for (int i = 0; i < 8; i++) {
            int r = row + i * 16;
            cp16(sQh + r * AQ_STRIDE + ch * 16, gq + r * 256 + ch * 16);
            cp16(sQl + r * AQ_STRIDE + ch * 16, gl + r * 256 + ch * 16);
        }
    }

#define LOADKV(kb_, p_)                                                              \
    do {                                                                             \
        uint32_t kvb_ = sKV + (p_) * KVBUF_BYTES;                                    \
        const char* gkh_ = (const char*)(Kbh + (bhd * SEQLEN + (kb_) * 64) * HDIM);  \
        const char* gkl_ = (const char*)(Kbl + (bhd * SEQLEN + (kb_) * 64) * HDIM);  \
        {                                                                            \
            int row_ = tid >> 4, ch_ = tid & 15;                                     \
            _Pragma("unroll")                                                        \
            for (int i_ = 0; i_ < 4; i_++) {                                         \
                int r_ = row_ + i_ * 16;                                             \
                cp16(kvb_ + r_ * AQ_STRIDE + ch_ * 16, gkh_ + r_ * 256 + ch_ * 16);  \
                cp16(kvb_ + K_BYTES + r_ * AQ_STRIDE + ch_ * 16,                     \
                     gkl_ + r_ * 256 + ch_ * 16);                                    \
            }                                                                        \
        }                                                                            \
        const char* gvh_ = (const char*)(Vth + bhd * HDIM * SEQLEN + (kb_) * 64);    \
        const char* gvl_ = (const char*)(Vtl + bhd * HDIM * SEQLEN + (kb_) * 64);    \
        {                                                                            \
            int row_ = tid >> 3, ch_ = tid & 7;                                      \
            _Pragma("unroll")                                                        \
            for (int i_ = 0; i_ < 4; i_++) {                                         \
                int r_ = row_ + i_ * 32;                                             \
                cp16(kvb_ + 2 * K_BYTES + r_ * AV_STRIDE + ch_ * 16,                 \
                     gvh_ + (size_t)r_ * SEQLEN * 2 + ch_ * 16);                     \
                cp16(kvb_ + 2 * K_BYTES + VT_BYTES + r_ * AV_STRIDE + ch_ * 16,      \
                     gvl_ + (size_t)r_ * SEQLEN * 2 + ch_ * 16);                     \
            }                                                                        \
        }                                                                            \
        asm volatile("cp.async.commit_group;" ::: "memory");                         \
    } while (0)

    const int nt = 2 * qt + 2;
    LOADKV(0, 0);
    LOADKV(1, 1);

    const uint32_t aQoff = (warp * 16 + (lane & 15)) * AQ_STRIDE + ((lane >> 4) << 4);
    const uint32_t bKoff = ((lane & 7) + ((lane & 16) >> 1)) * AQ_STRIDE + (lane & 8) * 2;
    const uint32_t bVoff = ((lane & 7) + ((lane & 16) >> 1)) * AV_STRIDE + (lane & 8) * 2;

    float o[16][4];
#pragma unroll
    for (int j = 0; j < 16; j++)
#pragma unroll
        for (int c = 0; c < 4; c++) o[j][c] = 0.f;
    float m_run[2] = {-1e30f, -1e30f}, l_run[2] = {0.f, 0.f};

    for (int kb = 0; kb < nt; kb++) {
        const uint32_t kvb = sKV + (kb & 1) * KVBUF_BYTES;
        if (kb + 1 < nt) asm volatile("cp.async.wait_group 1;" ::: "memory");
        else             asm volatile("cp.async.wait_group 0;" ::: "memory");
        __syncthreads();

        float s[8][4];
#pragma unroll
        for (int j = 0; j < 8; j++)
#pragma unroll
            for (int c = 0; c < 4; c++) s[j][c] = 0.f;

#pragma unroll
        for (int ks = 0; ks < 8; ks++) {
            uint32_t ah[4], al[4];
            ldsm4(ah, sQh + aQoff + ks * 32);
            ldsm4(al, sQl + aQoff + ks * 32);
#pragma unroll
            for (int nb = 0; nb < 4; nb++) {
                uint32_t kh4[4], kl4[4];
                ldsm4(kh4, kvb + bKoff + nb * 16 * AQ_STRIDE + ks * 32);
                ldsm4(kl4, kvb + K_BYTES + bKoff + nb * 16 * AQ_STRIDE + ks * 32);
                mma16816(s[nb * 2], ah, kh4);
                mma16816(s[nb * 2], al, kh4);
                mma16816(s[nb * 2], ah, kl4);
                mma16816(s[nb * 2 + 1], ah, kh4 + 2);
                mma16816(s[nb * 2 + 1], al, kh4 + 2);
                mma16816(s[nb * 2 + 1], ah, kl4 + 2);
            }
        }

        if (kb >= 2 * qt) {
            int r0 = qt * 128 + warp * 16 + (lane >> 2);
            int c0 = kb * 64 + (lane & 3) * 2;
#pragma unroll
            for (int j = 0; j < 8; j++)
#pragma unroll
                for (int c = 0; c < 4; c++) {
                    int col = c0 + j * 8 + (c & 1);
                    int row = r0 + ((c & 2) ? 8 : 0);
                    if (col > row) s[j][c] = -1e30f;
                }
        }

        float mloc[2] = {-1e30f, -1e30f};
#pragma unroll
        for (int j = 0; j < 8; j++) {
            mloc[0] = fmaxf(mloc[0], fmaxf(s[j][0], s[j][1]));
            mloc[1] = fmaxf(mloc[1], fmaxf(s[j][2], s[j][3]));
        }
        float mnew[2], alpha[2], rs[2];
#pragma unroll
        for (int h2 = 0; h2 < 2; h2++) {
            mloc[h2] = fmaxf(mloc[h2], __shfl_xor_sync(0xffffffffu, mloc[h2], 1));
            mloc[h2] = fmaxf(mloc[h2], __shfl_xor_sync(0xffffffffu, mloc[h2], 2));
            mnew[h2] = fmaxf(m_run[h2], mloc[h2]);
            alpha[h2] = exp2f(m_run[h2] - mnew[h2]);
            rs[h2] = 0.f;
        }
#pragma unroll
        for (int j = 0; j < 8; j++) {
            s[j][0] = exp2f(s[j][0] - mnew[0]);
            s[j][1] = exp2f(s[j][1] - mnew[0]);
            s[j][2] = exp2f(s[j][2] - mnew[1]);
            s[j][3] = exp2f(s[j][3] - mnew[1]);
            rs[0] += s[j][0] + s[j][1];
            rs[1] += s[j][2] + s[j][3];
        }
#pragma unroll
        for (int h2 = 0; h2 < 2; h2++) {
            rs[h2] += __shfl_xor_sync(0xffffffffu, rs[h2], 1);
            rs[h2] += __shfl_xor_sync(0xffffffffu, rs[h2], 2);
            l_run[h2] = l_run[h2] * alpha[h2] + rs[h2];
            m_run[h2] = mnew[h2];
        }
#pragma unroll
        for (int j = 0; j < 16; j++) {
            o[j][0] *= alpha[0];
            o[j][1] *= alpha[0];
            o[j][2] *= alpha[1];
            o[j][3] *= alpha[1];
        }

#pragma unroll
        for (int kc = 0; kc < 4; kc++) {
            uint32_t pah[4], pal[4];
            split2(s[2 * kc][0], s[2 * kc][1], pah[0], pal[0]);
            split2(s[2 * kc][2], s[2 * kc][3], pah[1], pal[1]);
            split2(s[2 * kc + 1][0], s[2 * kc + 1][1], pah[2], pal[2]);
            split2(s[2 * kc + 1][2], s[2 * kc + 1][3], pah[3], pal[3]);
#pragma unroll
            for (int nb = 0; nb < 8; nb++) {
                uint32_t vh4[4], vl4[4];
                ldsm4(vh4, kvb + 2 * K_BYTES + bVoff + nb * 16 * AV_STRIDE + kc * 32);
                ldsm4(vl4, kvb + 2 * K_BYTES + VT_BYTES + bVoff + nb * 16 * AV_STRIDE + kc * 32);
                mma16816(o[nb * 2], pah, vh4);
                mma16816(o[nb * 2], pal, vh4);
                mma16816(o[nb * 2], pah, vl4);
                mma16816(o[nb * 2 + 1], pah, vh4 + 2);
                mma16816(o[nb * 2 + 1], pal, vh4 + 2);
                mma16816(o[nb * 2 + 1], pah, vl4 + 2);
            }
        }

        if (kb + 2 < nt) {
            __syncthreads();
            LOADKV(kb + 2, kb & 1);
        }
    }

    // normalize + write fp32 [token][dim]
    float inv[2] = {1.f / l_run[0], 1.f / l_run[1]};
    size_t trow = (size_t)b * SEQLEN + qt * 128 + warp * 16 + (lane >> 2);
#pragma unroll
    for (int j = 0; j < 16; j++) {
        int c0 = j * 8 + (lane & 3) * 2;
#pragma unroll
        for (int h2 = 0; h2 < 2; h2++) {
            size_t t = trow + h2 * 8;
            float2 v = {o[j][h2 * 2] * inv[h2], o[j][h2 * 2 + 1] * inv[h2]};
            *(float2*)(O + t * DIM + h * HDIM + c0) = v;
        }
    }
}

// ---------------------------------------------------------------------------
extern "C" void kernel_launch(void* const* d_in, const int* in_sizes, int n_in,
                              void* d_out, int out_size) {
    const float* x  = (const float*)d_in[0];
    const float* fc = (const float*)d_in[1];
    const float* w[4] = {(const float*)d_in[4], (const float*)d_in[5],
                         (const float*)d_in[6], (const float*)d_in[7]};

    float* out = (float*)d_out;
    float* Kh = out + OUT_ELEMS;
    float* Vh = Kh + OUT_ELEMS;

    float *qbuf, *attnf, *sX, *sW;
    int8_t *a8h, *a8l, *w8h, *w8l;
    __nv_bfloat16 *qh, *ql, *kbh, *kbl, *vth, *vtl;
    cudaGetSymbolAddress((void**)&qbuf, g_Q);
    cudaGetSymbolAddress((void**)&attnf, g_attn);
    cudaGetSymbolAddress((void**)&a8h, g_a8h);
    cudaGetSymbolAddress((void**)&a8l, g_a8l);
    cudaGetSymbolAddress((void**)&w8h, g_w8h);
    cudaGetSymbolAddress((void**)&w8l, g_w8l);
    cudaGetSymbolAddress((void**)&sX, g_sX);
    cudaGetSymbolAddress((void**)&sW, g_sW);
    cudaGetSymbolAddress((void**)&qh, g_qh);
    cudaGetSymbolAddress((void**)&ql, g_ql);
    cudaGetSymbolAddress((void**)&kbh, g_kh);
    cudaGetSymbolAddress((void**)&kbl, g_kl);
    cudaGetSymbolAddress((void**)&vth, g_vth);
    cudaGetSymbolAddress((void**)&vtl, g_vtl);

    quant_rows<<<DIM, 128>>>(x, a8h, a8l, sX);
    for (int m = 0; m < 4; m++)
        quant_rows<<<DIM, 128>>>(w[m], w8h + m * WSZ, w8l + m * WSZ, sW + m * DIM);

    cudaFuncSetAttribute(gemm_i8, cudaFuncAttributeMaxDynamicSharedMemorySize, I8_SMEM);

    // Fused QKV projection (B tiles 0..95 span wq, wk, wv)
    gemm_i8<<<dim3(96, 32), 256, I8_SMEM>>>(a8h, a8l, w8h, w8l, sX, sW, qbuf, Kh, Vh);

    int rtotal = BSZ * SEQLEN * NHEADS * (HDIM / 2);
    rotary_convert<<<rtotal / 256, 256>>>(qbuf, Kh, fc, qh, ql, kbh, kbl);
    v_transpose<<<dim3(SEQLEN / 32, HDIM / 32, BSZ * NHEADS), dim3(32, 8)>>>(Vh, vth, vtl);

    cudaFuncSetAttribute(flash_attn, cudaFuncAttributeMaxDynamicSharedMemorySize, ATTN_SMEM);
    flash_attn<<<dim3(SEQLEN / 128, NHEADS, BSZ), 256, ATTN_SMEM>>>(
        qh, ql, kbh, kbl, vth, vtl, attnf);

    // quantize attention output (reuses x digit buffers + scale)
    quant_rows<<<DIM, 128>>>(attnf, a8h, a8l, sX);

    // Output projection
    gemm_i8<<<dim3(32, 32), 256, I8_SMEM>>>(a8h, a8l, w8h + 3 * WSZ, w8l + 3 * WSZ,
                                            sX, sW + 3 * DIM, out, out, out);
}

// round 9
// speedup vs baseline: 3.8144x; 3.8144x over previous
#include <cuda_runtime.h>
#include <cuda_bf16.h>
#include <cuda_fp16.h>
#include <cstdint>

#define BSZ 2
#define SEQLEN 2048
#define NHEADS 32
#define HDIM 128
#define DIM 4096
#define NTOK (BSZ * SEQLEN)              // 4096
#define OUT_ELEMS ((size_t)NTOK * DIM)   // 16,777,216
#define WSZ ((size_t)DIM * DIM)

// ---------------- GEMM tiling: 256x128 CTA tile, BK=32, pre-tiled GMEM -------
#define BK 32
#define CHUNKS (DIM / BK)                // 128
#define A_TILE_B 16384                   // 256 rows x 64 B
#define B_TILE_B 8192                    // 128 rows x 64 B
#define STAGE_B (2 * A_TILE_B + B_TILE_B)       // Ah, Al, Bh = 40960
#define NSTAGE 4
#define GEMM_SMEM (NSTAGE * STAGE_B + 64)       // 163904 B

// ---------------- attention tiling (unchanged, bf16 3-term) ----------------
#define AQ_STRIDE 272
#define AV_STRIDE 144
#define Q_BYTES (128 * AQ_STRIDE)
#define K_BYTES (64 * AQ_STRIDE)
#define VT_BYTES (128 * AV_STRIDE)
#define KVBUF_BYTES (2 * K_BYTES + 2 * VT_BYTES)
#define ATTN_SMEM (2 * Q_BYTES + 2 * KVBUF_BYTES)  // 212992

// ---------------- scratch (device globals; no allocation allowed) -----------
__device__ __align__(256) float g_Q[OUT_ELEMS];
__device__ __align__(256) __half g_xh[OUT_ELEMS];       // x digits (A layout)
__device__ __align__(256) __half g_xl[OUT_ELEMS];
__device__ __align__(256) __half g_wh[4ull * WSZ];      // weight hi (B layout)
__device__ __align__(256) __half g_ah[OUT_ELEMS];       // attn-out digits (A layout)
__device__ __align__(256) __half g_al[OUT_ELEMS];
__device__ __align__(256) __nv_bfloat16 g_qh[OUT_ELEMS];
__device__ __align__(256) __nv_bfloat16 g_ql[OUT_ELEMS];
__device__ __align__(256) __nv_bfloat16 g_kh[OUT_ELEMS];
__device__ __align__(256) __nv_bfloat16 g_kl[OUT_ELEMS];
__device__ __align__(256) __nv_bfloat16 g_vth[OUT_ELEMS];
__device__ __align__(256) __nv_bfloat16 g_vtl[OUT_ELEMS];

// ---------------- PTX helpers ------------------------------------------------
__device__ __forceinline__ uint32_t smem_u32(const void* p) {
    uint32_t a;
    asm("{ .reg .u64 t; cvta.to.shared.u64 t, %1; cvt.u32.u64 %0, t; }" : "=r"(a) : "l"(p));
    return a;
}
__device__ __forceinline__ void cp16(uint32_t dst, const void* src) {
    asm volatile("cp.async.cg.shared.global [%0], [%1], 16;" :: "r"(dst), "l"(src));
}
__device__ __forceinline__ void bulk_cp(uint32_t dst, const void* src, uint32_t bytes,
                                        uint32_t mbar) {
    asm volatile(
        "cp.async.bulk.shared::cta.global.mbarrier::complete_tx::bytes [%0], [%1], %2, [%3];"
        :: "r"(dst), "l"(src), "r"(bytes), "r"(mbar) : "memory");
}
__device__ __forceinline__ void mbar_expect(uint32_t mbar, uint32_t bytes) {
    asm volatile("mbarrier.arrive.expect_tx.shared.b64 _, [%0], %1;"
                 :: "r"(mbar), "r"(bytes) : "memory");
}
__device__ __forceinline__ void mbar_wait(uint32_t mbar, uint32_t parity) {
    asm volatile(
        "{\n\t.reg .pred P;\n\t"
        "LAB%=:\n\t"
        "mbarrier.try_wait.parity.acquire.cta.shared::cta.b64 P, [%0], %1, 0x989680;\n\t"
        "@!P bra LAB%=;\n\t}"
        :: "r"(mbar), "r"(parity) : "memory");
}
__device__ __forceinline__ void ldsm4(uint32_t* r, uint32_t addr) {
    asm volatile("ldmatrix.sync.aligned.m8n8.x4.shared.b16 {%0,%1,%2,%3}, [%4];"
        : "=r"(r[0]), "=r"(r[1]), "=r"(r[2]), "=r"(r[3]) : "r"(addr));
}
__device__ __forceinline__ void mma16816(float* c, const uint32_t* a, const uint32_t* b) {
    asm volatile("mma.sync.aligned.m16n8k16.row.col.f32.bf16.bf16.f32 "
        "{%0,%1,%2,%3}, {%4,%5,%6,%7}, {%8,%9}, {%0,%1,%2,%3};"
        : "+f"(c[0]), "+f"(c[1]), "+f"(c[2]), "+f"(c[3])
        : "r"(a[0]), "r"(a[1]), "r"(a[2]), "r"(a[3]), "r"(b[0]), "r"(b[1]));
}
__device__ __forceinline__ void mma_f16(float* c, const uint32_t* a, const uint32_t* b) {
    asm volatile("mma.sync.aligned.m16n8k16.row.col.f32.f16.f16.f32 "
        "{%0,%1,%2,%3}, {%4,%5,%6,%7}, {%8,%9}, {%0,%1,%2,%3};"
        : "+f"(c[0]), "+f"(c[1]), "+f"(c[2]), "+f"(c[3])
        : "r"(a[0]), "r"(a[1]), "r"(a[2]), "r"(a[3]), "r"(b[0]), "r"(b[1]));
}
__device__ __forceinline__ void split2(float a, float b, uint32_t& hi, uint32_t& lo) {
    __nv_bfloat162 h = __floats2bfloat162_rn(a, b);
    float ra = a - __bfloat162float(h.x);
    float rb = b - __bfloat162float(h.y);
    __nv_bfloat162 l = __floats2bfloat162_rn(ra, rb);
    hi = *(uint32_t*)&h;
    lo = *(uint32_t*)&l;
}
__device__ __forceinline__ void split2h(float a, float b, uint32_t& hi, uint32_t& lo) {
    __half2 h = __floats2half2_rn(a, b);
    float ra = a - __half2float(__low2half(h));
    float rb = b - __half2float(__high2half(h));
    __half2 l = __floats2half2_rn(ra, rb);
    hi = *(uint32_t*)&h;
    lo = *(uint32_t*)&l;
}

// ---------------------------------------------------------------------------
// x (fp32) -> fp16 hi/lo digits, A layout (256-row tiles):
// off = ((mt*128+ck)*256 + rr)*64 + (c16 ^ ((rr>>1)&3))*16
// ---------------------------------------------------------------------------
__global__ __launch_bounds__(256) void convert_A(const float* __restrict__ src,
                                                 __half* __restrict__ hi,
                                                 __half* __restrict__ lo) {
    int idx = blockIdx.x * 256 + threadIdx.x;
    int r = idx >> 9;
    int k = (idx & 511) << 3;
    const float4* s = (const float4*)(src + ((size_t)r << 12) + k);
    float4 v0 = s[0], v1 = s[1];
    float f[8] = {v0.x, v0.y, v0.z, v0.w, v1.x, v1.y, v1.z, v1.w};
    __half h8[8], l8[8];
#pragma unroll
    for (int j = 0; j < 8; j++) {
        h8[j] = __float2half_rn(f[j]);
        l8[j] = __float2half_rn(f[j] - __half2float(h8[j]));
    }
    int mt = r >> 8, rr = r & 255, ck = k >> 5, c16 = (k & 31) >> 3;
    size_t off = ((((size_t)(mt * 128 + ck)) * 256 + rr) << 6) +
                 ((c16 ^ ((rr >> 1) & 3)) << 4);
    *(uint4*)((char*)hi + off) = *(uint4*)h8;
    *(uint4*)((char*)lo + off) = *(uint4*)l8;
}

// ---------------------------------------------------------------------------
// weights (fp32) -> fp16 hi only, B layout (128-row tiles). blockIdx.y = matrix.
// ---------------------------------------------------------------------------
__global__ __launch_bounds__(256) void convert_W(
        const float* __restrict__ w0, const float* __restrict__ w1,
        const float* __restrict__ w2, const float* __restrict__ w3,
        __half* __restrict__ out) {
    int m = blockIdx.y;
    const float* src = (m == 0) ? w0 : (m == 1) ? w1 : (m == 2) ? w2 : w3;
    __half* hi = out + (size_t)m * WSZ;

    int idx = blockIdx.x * 256 + threadIdx.x;
    int r = idx >> 9;
    int k = (idx & 511) << 3;
    const float4* s = (const float4*)(src + ((size_t)r << 12) + k);
    float4 v0 = s[0], v1 = s[1];
    float f[8] = {v0.x, v0.y, v0.z, v0.w, v1.x, v1.y, v1.z, v1.w};
    __half h8[8];
#pragma unroll
    for (int j = 0; j < 8; j++) h8[j] = __float2half_rn(f[j]);
    int nt = r >> 7, rr = r & 127, ck = k >> 5, c16 = (k & 31) >> 3;
    size_t off = ((((size_t)(nt * 128 + ck)) * 128 + rr) << 6) +
                 ((c16 ^ ((rr >> 1) & 3)) << 4);
    *(uint4*)((char*)hi + off) = *(uint4*)h8;
}

// ---------------------------------------------------------------------------
// fp16 2-term GEMM: C = Ah.Bh + Al.Bh (B truncated to fp16 hi).
// 256x128 CTA tile, BK=32, 4-stage cp.async.bulk pipeline, 8 warps of 64x64.
// Output routed to C0/C1/C2 by nt>>5 (fused QKV).
// ---------------------------------------------------------------------------
__global__ __launch_bounds__(256)
void gemm_f16(const __half* __restrict__ Ah, const __half* __restrict__ Al,
              const __half* __restrict__ Bh,
              float* __restrict__ C0, float* __restrict__ C1, float* __restrict__ C2) {
    extern __shared__ char sm_raw[];
    const uint32_t base = smem_u32(sm_raw);
    const uint32_t mb = base + NSTAGE * STAGE_B;
    const int tid = threadIdx.x;
    const int warp = tid >> 5, lane = tid & 31;
    const int wm = warp & 3, wn = warp >> 2;     // 4 x 2 warp grid, warp 64x64
    const int nt = blockIdx.x, mt = blockIdx.y;
    const size_t mtC = (size_t)mt * CHUNKS;
    const size_t ntC = (size_t)nt * CHUNKS;

    if (tid == 0) {
#pragma unroll
        for (int s = 0; s < NSTAGE; s++)
            asm volatile("mbarrier.init.shared.b64 [%0], %1;" :: "r"(mb + 8 * s), "r"(1u) : "memory");
        asm volatile("fence.proxy.async.shared::cta;" ::: "memory");
    }
    __syncthreads();

#define ISSUE(c, s)                                                              \
    do {                                                                         \
        if (tid == 0) {                                                          \
            uint32_t mb_ = mb + 8 * (s);                                         \
            mbar_expect(mb_, STAGE_B);                                           \
            uint32_t st_ = base + (s) * STAGE_B;                                 \
            bulk_cp(st_, (const char*)Ah + (mtC + (c)) * A_TILE_B, A_TILE_B, mb_); \
            bulk_cp(st_ + A_TILE_B, (const char*)Al + (mtC + (c)) * A_TILE_B, A_TILE_B, mb_); \
            bulk_cp(st_ + 2 * A_TILE_B, (const char*)Bh + (ntC + (c)) * B_TILE_B, B_TILE_B, mb_); \
        }                                                                        \
    } while (0)

    ISSUE(0, 0);
    ISSUE(1, 1);
    ISSUE(2, 2);

    // per-thread ldsm address components (swizzled 64B rows)
    const int rowA = wm * 64 + (lane & 15);
    const int xa = (rowA >> 1) & 3;
    const int lsA = lane >> 4;
    const uint32_t cA0 = (uint32_t)((lsA ^ xa) << 4);
    const uint32_t cA1 = (uint32_t)(((2 | lsA) ^ xa) << 4);
    const uint32_t aRow = (uint32_t)rowA * 64;

    const int rowB = wn * 64 + (lane & 7) + ((lane & 16) >> 1);
    const int xb = (rowB >> 1) & 3;
    const int lsB = (lane & 8) >> 3;
    const uint32_t cB0 = (uint32_t)((lsB ^ xb) << 4);
    const uint32_t cB1 = (uint32_t)(((2 | lsB) ^ xb) << 4);
    const uint32_t bRow = (uint32_t)rowB * 64;

    float c[4][8][4];
#pragma unroll
    for (int mi = 0; mi < 4; mi++)
#pragma unroll
        for (int ni = 0; ni < 8; ni++)
#pragma unroll
            for (int j = 0; j < 4; j++) c[mi][ni][j] = 0.f;

    for (int ck = 0; ck < CHUNKS; ck++) {
        const int s = ck & 3;
        mbar_wait(mb + 8 * s, (ck >> 2) & 1);

        const uint32_t sb = base + s * STAGE_B;
        const uint32_t aHi = sb + aRow;
        const uint32_t aLo = aHi + A_TILE_B;
        const uint32_t bHi = sb + 2 * A_TILE_B + bRow;

#pragma unroll
        for (int kk = 0; kk < 2; kk++) {
            const uint32_t ca = kk ? cA1 : cA0;
            const uint32_t cb = kk ? cB1 : cB0;
            uint32_t bh[16];
#pragma unroll
            for (int g = 0; g < 4; g++) ldsm4(bh + g * 4, bHi + g * 1024 + cb);
#pragma unroll
            for (int mi = 0; mi < 4; mi++) {
                uint32_t ah[4], al[4];
                ldsm4(ah, aHi + mi * 1024 + ca);
                ldsm4(al, aLo + mi * 1024 + ca);
#pragma unroll
                for (int ni = 0; ni < 8; ni++) {
                    mma_f16(c[mi][ni], ah, &bh[ni * 2]);
                    mma_f16(c[mi][ni], al, &bh[ni * 2]);
                }
            }
        }
        __syncthreads();
        if (ck + 3 < CHUNKS) ISSUE(ck + 3, (ck + 3) & 3);
    }

    // epilogue: route by nt>>5 (fused QKV), col block = (nt & 31) * 128
    float* Cb = (nt < 32) ? C0 : (nt < 64) ? C1 : C2;
    float* Cw = Cb + (size_t)(mt * 256 + wm * 64) * DIM + (nt & 31) * 128 + wn * 64;
    const int cr = lane >> 2, cc = (lane & 3) * 2;
#pragma unroll
    for (int mi = 0; mi < 4; mi++)
#pragma unroll
        for (int ni = 0; ni < 8; ni++) {
            float* p0 = Cw + (size_t)(mi * 16 + cr) * DIM + ni * 8 + cc;
            float* p1 = p0 + 8 * DIM;
            *(float2*)p0 = make_float2(c[mi][ni][0], c[mi][ni][1]);
            *(float2*)p1 = make_float2(c[mi][ni][2], c[mi][ni][3]);
        }
}

// ---------------------------------------------------------------------------
// Rotary + bf16 split for Q (scaled by log2e/sqrt(d)) and K. (unchanged)
// ---------------------------------------------------------------------------
__global__ __launch_bounds__(256) void rotary_convert(
        const float* __restrict__ Q, float* __restrict__ Kf,
        const float* __restrict__ fc,
        __nv_bfloat16* __restrict__ qh, __nv_bfloat16* __restrict__ ql,
        __nv_bfloat16* __restrict__ kh, __nv_bfloat16* __restrict__ kl) {
    const float QSC = 1.44269504088896f / 11.3137084989848f;
    int idx = blockIdx.x * blockDim.x + threadIdx.x;
    int p = idx & 63;
    int h = (idx >> 6) & 31;
    int s = (idx >> 11) & (SEQLEN - 1);
    int b = idx >> 22;

    float c = fc[(s * 64 + p) * 2];
    float sn = fc[(s * 64 + p) * 2 + 1];

    size_t in = (((size_t)(b * SEQLEN + s) * NHEADS) + h) * HDIM + p * 2;
    size_t out = (((size_t)(b * NHEADS + h) * SEQLEN) + s) * HDIM + p * 2;

    float2 q = *(float2*)(Q + in);
    float2 k = *(float2*)(Kf + in);
    float2 qo = {q.x * c - q.y * sn, q.x * sn + q.y * c};
    float2 ko = {k.x * c - k.y * sn, k.x * sn + k.y * c};
    *(float2*)(Kf + in) = ko;

    uint32_t hi, lo;
    split2(qo.x * QSC, qo.y * QSC, hi, lo);
    *(uint32_t*)(qh + out) = hi;
    *(uint32_t*)(ql + out) = lo;
    split2(ko.x, ko.y, hi, lo);
    *(uint32_t*)(kh + out) = hi;
    *(uint32_t*)(kl + out) = lo;
}

// ---------------------------------------------------------------------------
// V transpose + split (unchanged)
// ---------------------------------------------------------------------------
__global__ __launch_bounds__(256) void v_transpose(const float* __restrict__ V,
                                                   __nv_bfloat16* __restrict__ vth,
                                                   __nv_bfloat16* __restrict__ vtl) {
    __shared__ float t[32][33];
    int s0 = blockIdx.x * 32, d0 = blockIdx.y * 32;
    int bh = blockIdx.z;
    int b = bh >> 5, h = bh & 31;
#pragma unroll
    for (int i = 0; i < 4; i++) {
        int s = s0 + threadIdx.y + i * 8;
        t[threadIdx.y + i * 8][threadIdx.x] =
            V[(((size_t)(b * SEQLEN + s) * NHEADS) + h) * HDIM + d0 + threadIdx.x];
    }
    __syncthreads();
#pragma unroll
    for (int i = 0; i < 4; i++) {
        int d = d0 + threadIdx.y + i * 8;
        float v = t[threadIdx.x][threadIdx.y + i * 8];
        __nv_bfloat16 hb = __float2bfloat16(v);
        size_t o = ((size_t)bh * HDIM + d) * SEQLEN + s0 + threadIdx.x;
        vth[o] = hb;
        vtl[o] = __float2bfloat16(v - __bfloat162float(hb));
    }
}

// ---------------------------------------------------------------------------
// Flash attention, split-bf16 mma.sync (unchanged math). Epilogue writes
// fp16 hi/lo digits in the 256-row tiled A layout for the Wo GEMM.
// ---------------------------------------------------------------------------
__global__ __launch_bounds__(256)
void flash_attn(const __nv_bfloat16* __restrict__ Qh, const __nv_bfloat16* __restrict__ Ql,
                const __nv_bfloat16* __restrict__ Kbh, const __nv_bfloat16* __restrict__ Kbl,
                const __nv_bfloat16* __restrict__ Vth, const __nv_bfloat16* __restrict__ Vtl,
                __half* __restrict__ Oh, __half* __restrict__ Ol) {
    extern __shared__ char sm_raw[];
    const uint32_t base = smem_u32(sm_raw);
    const int tid = threadIdx.x, warp = tid >> 5, lane = tid & 31;
    const int qt = blockIdx.x, h = blockIdx.y, b = blockIdx.z;
    const size_t bhd = (size_t)(b * NHEADS + h);

    const uint32_t sQh = base, sQl = base + Q_BYTES;
    const uint32_t sKV = base + 2 * Q_BYTES;

    {
        const char* gq = (const char*)(Qh + (bhd * SEQLEN + qt * 128) * HDIM);
        const char* gl = (const char*)(Ql + (bhd * SEQLEN + qt * 128) * HDIM);
        int row = tid >> 4, ch = tid & 15;
#pragma unroll
        for (int i = 0; i < 8; i++) {
            int r = row + i * 16;
            cp16(sQh + r * AQ_STRIDE + ch * 16, gq + r * 256 + ch * 16);
            cp16(sQl + r * AQ_STRIDE + ch * 16, gl + r * 256 + ch * 16);
        }
    }

#define LOADKV(kb_, p_)                                                              \
    do {                                                                             \
        uint32_t kvb_ = sKV + (p_) * KVBUF_BYTES;                                    \
        const char* gkh_ = (const char*)(Kbh + (bhd * SEQLEN + (kb_) * 64) * HDIM);  \
        const char* gkl_ = (const char*)(Kbl + (bhd * SEQLEN + (kb_) * 64) * HDIM);  \
        {                                                                            \
            int row_ = tid >> 4, ch_ = tid & 15;                                     \
            _Pragma("unroll")                                                        \
            for (int i_ = 0; i_ < 4; i_++) {                                         \
                int r_ = row_ + i_ * 16;                                             \
                cp16(kvb_ + r_ * AQ_STRIDE + ch_ * 16, gkh_ + r_ * 256 + ch_ * 16);  \
                cp16(kvb_ + K_BYTES + r_ * AQ_STRIDE + ch_ * 16,                     \
                     gkl_ + r_ * 256 + ch_ * 16);                                    \
            }                                                                        \
        }                                                                            \
        const char* gvh_ = (const char*)(Vth + bhd * HDIM * SEQLEN + (kb_) * 64);    \
        const char* gvl_ = (const char*)(Vtl + bhd * HDIM * SEQLEN + (kb_) * 64);    \
        {                                                                            \
            int row_ = tid >> 3, ch_ = tid & 7;                                      \
            _Pragma("unroll")                                                        \
            for (int i_ = 0; i_ < 4; i_++) {                                         \
                int r_ = row_ + i_ * 32;                                             \
                cp16(kvb_ + 2 * K_BYTES + r_ * AV_STRIDE + ch_ * 16,                 \
                     gvh_ + (size_t)r_ * SEQLEN * 2 + ch_ * 16);                     \
                cp16(kvb_ + 2 * K_BYTES + VT_BYTES + r_ * AV_STRIDE + ch_ * 16,      \
                     gvl_ + (size_t)r_ * SEQLEN * 2 + ch_ * 16);                     \
            }                                                                        \
        }                                                                            \
        asm volatile("cp.async.commit_group;" ::: "memory");                         \
    } while (0)

    const int nt = 2 * qt + 2;
    LOADKV(0, 0);
    LOADKV(1, 1);

    const uint32_t aQoff = (warp * 16 + (lane & 15)) * AQ_STRIDE + ((lane >> 4) << 4);
    const uint32_t bKoff = ((lane & 7) + ((lane & 16) >> 1)) * AQ_STRIDE + (lane & 8) * 2;
    const uint32_t bVoff = ((lane & 7) + ((lane & 16) >> 1)) * AV_STRIDE + (lane & 8) * 2;

    float o[16][4];
#pragma unroll
    for (int j = 0; j < 16; j++)
#pragma unroll
        for (int c = 0; c < 4; c++) o[j][c] = 0.f;
    float m_run[2] = {-1e30f, -1e30f}, l_run[2] = {0.f, 0.f};

    for (int kb = 0; kb < nt; kb++) {
        const uint32_t kvb = sKV + (kb & 1) * KVBUF_BYTES;
        if (kb + 1 < nt) asm volatile("cp.async.wait_group 1;" ::: "memory");
        else             asm volatile("cp.async.wait_group 0;" ::: "memory");
        __syncthreads();

        float s[8][4];
#pragma unroll
        for (int j = 0; j < 8; j++)
#pragma unroll
            for (int c = 0; c < 4; c++) s[j][c] = 0.f;

#pragma unroll
        for (int ks = 0; ks < 8; ks++) {
            uint32_t ah[4], al[4];
            ldsm4(ah, sQh + aQoff + ks * 32);
            ldsm4(al, sQl + aQoff + ks * 32);
#pragma unroll
            for (int nb = 0; nb < 4; nb++) {
                uint32_t kh4[4], kl4[4];
                ldsm4(kh4, kvb + bKoff + nb * 16 * AQ_STRIDE + ks * 32);
                ldsm4(kl4, kvb + K_BYTES + bKoff + nb * 16 * AQ_STRIDE + ks * 32);
                mma16816(s[nb * 2], ah, kh4);
                mma16816(s[nb * 2], al, kh4);
                mma16816(s[nb * 2], ah, kl4);
                mma16816(s[nb * 2 + 1], ah, kh4 + 2);
                mma16816(s[nb * 2 + 1], al, kh4 + 2);
                mma16816(s[nb * 2 + 1], ah, kl4 + 2);
            }
        }

        if (kb >= 2 * qt) {
            int r0 = qt * 128 + warp * 16 + (lane >> 2);
            int c0 = kb * 64 + (lane & 3) * 2;
#pragma unroll
            for (int j = 0; j < 8; j++)
#pragma unroll
                for (int c = 0; c < 4; c++) {
                    int col = c0 + j * 8 + (c & 1);
                    int row = r0 + ((c & 2) ? 8 : 0);
                    if (col > row) s[j][c] = -1e30f;
                }
        }

        float mloc[2] = {-1e30f, -1e30f};
#pragma unroll
        for (int j = 0; j < 8; j++) {
            mloc[0] = fmaxf(mloc[0], fmaxf(s[j][0], s[j][1]));
            mloc[1] = fmaxf(mloc[1], fmaxf(s[j][2], s[j][3]));
        }
        float mnew[2], alpha[2], rs[2];
#pragma unroll
        for (int h2 = 0; h2 < 2; h2++) {
            mloc[h2] = fmaxf(mloc[h2], __shfl_xor_sync(0xffffffffu, mloc[h2], 1));
            mloc[h2] = fmaxf(mloc[h2], __shfl_xor_sync(0xffffffffu, mloc[h2], 2));
            mnew[h2] = fmaxf(m_run[h2], mloc[h2]);
            alpha[h2] = exp2f(m_run[h2] - mnew[h2]);
            rs[h2] = 0.f;
        }
#pragma unroll
        for (int j = 0; j < 8; j++) {
            s[j][0] = exp2f(s[j][0] - mnew[0]);
            s[j][1] = exp2f(s[j][1] - mnew[0]);
            s[j][2] = exp2f(s[j][2] - mnew[1]);
            s[j][3] = exp2f(s[j][3] - mnew[1]);
            rs[0] += s[j][0] + s[j][1];
            rs[1] += s[j][2] + s[j][3];
        }
#pragma unroll
        for (int h2 = 0; h2 < 2; h2++) {
            rs[h2] += __shfl_xor_sync(0xffffffffu, rs[h2], 1);
            rs[h2] += __shfl_xor_sync(0xffffffffu, rs[h2], 2);
            l_run[h2] = l_run[h2] * alpha[h2] + rs[h2];
            m_run[h2] = mnew[h2];
        }
#pragma unroll
        for (int j = 0; j < 16; j++) {
            o[j][0] *= alpha[0];
            o[j][1] *= alpha[0];
            o[j][2] *= alpha[1];
            o[j][3] *= alpha[1];
        }

#pragma unroll
        for (int kc = 0; kc < 4; kc++) {
            uint32_t pah[4], pal[4];
            split2(s[2 * kc][0], s[2 * kc][1], pah[0], pal[0]);
            split2(s[2 * kc][2], s[2 * kc][3], pah[1], pal[1]);
            split2(s[2 * kc + 1][0], s[2 * kc + 1][1], pah[2], pal[2]);
            split2(s[2 * kc + 1][2], s[2 * kc + 1][3], pah[3], pal[3]);
#pragma unroll
            for (int nb = 0; nb < 8; nb++) {
                uint32_t vh4[4], vl4[4];
                ldsm4(vh4, kvb + 2 * K_BYTES + bVoff + nb * 16 * AV_STRIDE + kc * 32);
                ldsm4(vl4, kvb + 2 * K_BYTES + VT_BYTES + bVoff + nb * 16 * AV_STRIDE + kc * 32);
                mma16816(o[nb * 2], pah, vh4);
                mma16816(o[nb * 2], pal, vh4);
                mma16816(o[nb * 2], pah, vl4);
                mma16816(o[nb * 2 + 1], pah, vh4 + 2);
                mma16816(o[nb * 2 + 1], pal, vh4 + 2);
                mma16816(o[nb * 2 + 1], pah, vl4 + 2);
            }
        }

        if (kb + 2 < nt) {
            __syncthreads();
            LOADKV(kb + 2, kb & 1);
        }
    }

    // normalize + write fp16 hi/lo in 256-row tiled-A layout for the Wo GEMM
    float inv[2] = {1.f / l_run[0], 1.f / l_run[1]};
    int trow = b * SEQLEN + qt * 128 + warp * 16 + (lane >> 2);
#pragma unroll
    for (int j = 0; j < 16; j++) {
        int c0 = j * 8 + (lane & 3) * 2;
        int k = h * HDIM + c0;
        int ck = k >> 5, c16 = (k & 31) >> 3, bo = (k & 7) * 2;
#pragma unroll
        for (int h2 = 0; h2 < 2; h2++) {
            int t = trow + h2 * 8;
            int mtA = t >> 8, rr = t & 255;
            size_t off = ((((size_t)(mtA * 128 + ck)) * 256 + rr) << 6) +
                         ((c16 ^ ((rr >> 1) & 3)) << 4) + bo;
            float v0 = o[j][h2 * 2] * inv[h2];
            float v1 = o[j][h2 * 2 + 1] * inv[h2];
            uint32_t hi, lo;
            split2h(v0, v1, hi, lo);
            *(uint32_t*)((char*)Oh + off) = hi;
            *(uint32_t*)((char*)Ol + off) = lo;
        }
    }
}

// ---------------------------------------------------------------------------
extern "C" void kernel_launch(void* const* d_in, const int* in_sizes, int n_in,
                              void* d_out, int out_size) {
    const float* x  = (const float*)d_in[0];
    const float* fc = (const float*)d_in[1];
    const float* wq = (const float*)d_in[4];
    const float* wk = (const float*)d_in[5];
    const float* wv = (const float*)d_in[6];
    const float* wo = (const float*)d_in[7];

    float* out = (float*)d_out;
    float* Kh = out + OUT_ELEMS;
    float* Vh = Kh + OUT_ELEMS;

    float* qbuf;
    __half *xh, *xl, *wh, *ah, *al;
    __nv_bfloat16 *qh, *ql, *kbh, *kbl, *vth, *vtl;
    cudaGetSymbolAddress((void**)&qbuf, g_Q);
    cudaGetSymbolAddress((void**)&xh, g_xh);
    cudaGetSymbolAddress((void**)&xl, g_xl);
    cudaGetSymbolAddress((void**)&wh, g_wh);
    cudaGetSymbolAddress((void**)&ah, g_ah);
    cudaGetSymbolAddress((void**)&al, g_al);
    cudaGetSymbolAddress((void**)&qh, g_qh);
    cudaGetSymbolAddress((void**)&ql, g_ql);
    cudaGetSymbolAddress((void**)&kbh, g_kh);
    cudaGetSymbolAddress((void**)&kbl, g_kl);
    cudaGetSymbolAddress((void**)&vth, g_vth);
    cudaGetSymbolAddress((void**)&vtl, g_vtl);

    const int cblocks = (int)(WSZ / 8 / 256);   // 8 elems per thread

    convert_A<<<cblocks, 256>>>(x, xh, xl);
    convert_W<<<dim3(cblocks, 4), 256>>>(wq, wk, wv, wo, wh);

    cudaFuncSetAttribute(gemm_f16, cudaFuncAttributeMaxDynamicSharedMemorySize, GEMM_SMEM);

    // Fused QKV projection (B tiles 0..95 span wq, wk, wv)
    gemm_f16<<<dim3(96, NTOK / 256), 256, GEMM_SMEM>>>(xh, xl, wh, qbuf, Kh, Vh);

    int rtotal = BSZ * SEQLEN * NHEADS * (HDIM / 2);
    rotary_convert<<<rtotal / 256, 256>>>(qbuf, Kh, fc, qh, ql, kbh, kbl);
    v_transpose<<<dim3(SEQLEN / 32, HDIM / 32, BSZ * NHEADS), dim3(32, 8)>>>(Vh, vth, vtl);

    cudaFuncSetAttribute(flash_attn, cudaFuncAttributeMaxDynamicSharedMemorySize, ATTN_SMEM);
    flash_attn<<<dim3(SEQLEN / 128, NHEADS, BSZ), 256, ATTN_SMEM>>>(
        qh, ql, kbh, kbl, vth, vtl, ah, al);

    // Output projection (A = attention output in tiled layout)
    gemm_f16<<<dim3(32, NTOK / 256), 256, GEMM_SMEM>>>(
        ah, al, wh + 3 * WSZ, out, out, out);
}

// round 10
// speedup vs baseline: 5.7729x; 1.5134x over previous
#include <cuda_runtime.h>
#include <cuda_bf16.h>
#include <cuda_fp16.h>
#include <cstdint>

#define BSZ 2
#define SEQLEN 2048
#define NHEADS 32
#define HDIM 128
#define DIM 4096
#define NTOK (BSZ * SEQLEN)              // 4096
#define OUT_ELEMS ((size_t)NTOK * DIM)   // 16,777,216
#define WSZ ((size_t)DIM * DIM)

// ---------------- GEMM tiling: 256x128 CTA tile, BK=32, 1-term fp16 ---------
#define BK 32
#define CHUNKS (DIM / BK)                // 128
#define A_TILE_B 16384                   // 256 rows x 64 B
#define B_TILE_B 8192                    // 128 rows x 64 B
#define STAGE_B (A_TILE_B + B_TILE_B)    // 24576
#define NSTAGE 8
#define GEMM_SMEM (NSTAGE * STAGE_B + 64)       // 196672 B

// ---------------- attention tiling (unchanged, bf16 3-term) ----------------
#define AQ_STRIDE 272
#define AV_STRIDE 144
#define Q_BYTES (128 * AQ_STRIDE)
#define K_BYTES (64 * AQ_STRIDE)
#define VT_BYTES (128 * AV_STRIDE)
#define KVBUF_BYTES (2 * K_BYTES + 2 * VT_BYTES)
#define ATTN_SMEM (2 * Q_BYTES + 2 * KVBUF_BYTES)  // 212992

// ---------------- scratch (device globals; no allocation allowed) -----------
__device__ __align__(256) float g_Q[OUT_ELEMS];
__device__ __align__(256) __half g_xh[OUT_ELEMS];       // x fp16 (A layout)
__device__ __align__(256) __half g_wh[4ull * WSZ];      // weights fp16 (B layout)
__device__ __align__(256) __half g_ah[OUT_ELEMS];       // attn out fp16 (A layout)
__device__ __align__(256) __nv_bfloat16 g_qh[OUT_ELEMS];
__device__ __align__(256) __nv_bfloat16 g_ql[OUT_ELEMS];
__device__ __align__(256) __nv_bfloat16 g_kh[OUT_ELEMS];
__device__ __align__(256) __nv_bfloat16 g_kl[OUT_ELEMS];
__device__ __align__(256) __nv_bfloat16 g_vth[OUT_ELEMS];
__device__ __align__(256) __nv_bfloat16 g_vtl[OUT_ELEMS];

// ---------------- PTX helpers ------------------------------------------------
__device__ __forceinline__ uint32_t smem_u32(const void* p) {
    uint32_t a;
    asm("{ .reg .u64 t; cvta.to.shared.u64 t, %1; cvt.u32.u64 %0, t; }" : "=r"(a) : "l"(p));
    return a;
}
__device__ __forceinline__ void cp16(uint32_t dst, const void* src) {
    asm volatile("cp.async.cg.shared.global [%0], [%1], 16;" :: "r"(dst), "l"(src));
}
__device__ __forceinline__ void bulk_cp(uint32_t dst, const void* src, uint32_t bytes,
                                        uint32_t mbar) {
    asm volatile(
        "cp.async.bulk.shared::cta.global.mbarrier::complete_tx::bytes [%0], [%1], %2, [%3];"
        :: "r"(dst), "l"(src), "r"(bytes), "r"(mbar) : "memory");
}
__device__ __forceinline__ void mbar_expect(uint32_t mbar, uint32_t bytes) {
    asm volatile("mbarrier.arrive.expect_tx.shared.b64 _, [%0], %1;"
                 :: "r"(mbar), "r"(bytes) : "memory");
}
__device__ __forceinline__ void mbar_wait(uint32_t mbar, uint32_t parity) {
    asm volatile(
        "{\n\t.reg .pred P;\n\t"
        "LAB%=:\n\t"
        "mbarrier.try_wait.parity.acquire.cta.shared::cta.b64 P, [%0], %1, 0x989680;\n\t"
        "@!P bra LAB%=;\n\t}"
        :: "r"(mbar), "r"(parity) : "memory");
}
__device__ __forceinline__ void ldsm4(uint32_t* r, uint32_t addr) {
    asm volatile("ldmatrix.sync.aligned.m8n8.x4.shared.b16 {%0,%1,%2,%3}, [%4];"
        : "=r"(r[0]), "=r"(r[1]), "=r"(r[2]), "=r"(r[3]) : "r"(addr));
}
__device__ __forceinline__ void mma16816(float* c, const uint32_t* a, const uint32_t* b) {
    asm volatile("mma.sync.aligned.m16n8k16.row.col.f32.bf16.bf16.f32 "
        "{%0,%1,%2,%3}, {%4,%5,%6,%7}, {%8,%9}, {%0,%1,%2,%3};"
        : "+f"(c[0]), "+f"(c[1]), "+f"(c[2]), "+f"(c[3])
        : "r"(a[0]), "r"(a[1]), "r"(a[2]), "r"(a[3]), "r"(b[0]), "r"(b[1]));
}
__device__ __forceinline__ void mma_f16(float* c, const uint32_t* a, const uint32_t* b) {
    asm volatile("mma.sync.aligned.m16n8k16.row.col.f32.f16.f16.f32 "
        "{%0,%1,%2,%3}, {%4,%5,%6,%7}, {%8,%9}, {%0,%1,%2,%3};"
        : "+f"(c[0]), "+f"(c[1]), "+f"(c[2]), "+f"(c[3])
        : "r"(a[0]), "r"(a[1]), "r"(a[2]), "r"(a[3]), "r"(b[0]), "r"(b[1]));
}
__device__ __forceinline__ void split2(float a, float b, uint32_t& hi, uint32_t& lo) {
    __nv_bfloat162 h = __floats2bfloat162_rn(a, b);
    float ra = a - __bfloat162float(h.x);
    float rb = b - __bfloat162float(h.y);
    __nv_bfloat162 l = __floats2bfloat162_rn(ra, rb);
    hi = *(uint32_t*)&h;
    lo = *(uint32_t*)&l;
}

// ---------------------------------------------------------------------------
// x (fp32) -> fp16, A layout (256-row tiles):
// off = ((mt*128+ck)*256 + rr)*64 + (c16 ^ ((rr>>1)&3))*16
// ---------------------------------------------------------------------------
__global__ __launch_bounds__(256) void convert_A(const float* __restrict__ src,
                                                 __half* __restrict__ hi) {
    int idx = blockIdx.x * 256 + threadIdx.x;
    int r = idx >> 9;
    int k = (idx & 511) << 3;
    const float4* s = (const float4*)(src + ((size_t)r << 12) + k);
    float4 v0 = s[0], v1 = s[1];
    float f[8] = {v0.x, v0.y, v0.z, v0.w, v1.x, v1.y, v1.z, v1.w};
    __half h8[8];
#pragma unroll
    for (int j = 0; j < 8; j++) h8[j] = __float2half_rn(f[j]);
    int mt = r >> 8, rr = r & 255, ck = k >> 5, c16 = (k & 31) >> 3;
    size_t off = ((((size_t)(mt * 128 + ck)) * 256 + rr) << 6) +
                 ((c16 ^ ((rr >> 1) & 3)) << 4);
    *(uint4*)((char*)hi + off) = *(uint4*)h8;
}

// ---------------------------------------------------------------------------
// weights (fp32) -> fp16, B layout (128-row tiles). blockIdx.y = matrix.
// ---------------------------------------------------------------------------
__global__ __launch_bounds__(256) void convert_W(
        const float* __restrict__ w0, const float* __restrict__ w1,
        const float* __restrict__ w2, const float* __restrict__ w3,
        __half* __restrict__ out) {
    int m = blockIdx.y;
    const float* src = (m == 0) ? w0 : (m == 1) ? w1 : (m == 2) ? w2 : w3;
    __half* hi = out + (size_t)m * WSZ;

    int idx = blockIdx.x * 256 + threadIdx.x;
    int r = idx >> 9;
    int k = (idx & 511) << 3;
    const float4* s = (const float4*)(src + ((size_t)r << 12) + k);
    float4 v0 = s[0], v1 = s[1];
    float f[8] = {v0.x, v0.y, v0.z, v0.w, v1.x, v1.y, v1.z, v1.w};
    __half h8[8];
#pragma unroll
    for (int j = 0; j < 8; j++) h8[j] = __float2half_rn(f[j]);
    int nt = r >> 7, rr = r & 127, ck = k >> 5, c16 = (k & 31) >> 3;
    size_t off = ((((size_t)(nt * 128 + ck)) * 128 + rr) << 6) +
                 ((c16 ^ ((rr >> 1) & 3)) << 4);
    *(uint4*)((char*)hi + off) = *(uint4*)h8;
}

// ---------------------------------------------------------------------------
// fp16 1-term GEMM: C = A.B (both rn-truncated to fp16).
// 256x128 CTA tile, BK=32, 8-stage cp.async.bulk pipeline, 8 warps of 64x64.
// Output routed to C0/C1/C2 by nt>>5 (fused QKV).
// ---------------------------------------------------------------------------
__global__ __launch_bounds__(256)
void gemm_f16(const __half* __restrict__ Ah, const __half* __restrict__ Bh,
              float* __restrict__ C0, float* __restrict__ C1, float* __restrict__ C2) {
    extern __shared__ char sm_raw[];
    const uint32_t base = smem_u32(sm_raw);
    const uint32_t mb = base + NSTAGE * STAGE_B;
    const int tid = threadIdx.x;
    const int warp = tid >> 5, lane = tid & 31;
    const int wm = warp & 3, wn = warp >> 2;     // 4 x 2 warp grid, warp 64x64
    const int nt = blockIdx.x, mt = blockIdx.y;
    const size_t mtC = (size_t)mt * CHUNKS;
    const size_t ntC = (size_t)nt * CHUNKS;

    if (tid == 0) {
#pragma unroll
        for (int s = 0; s < NSTAGE; s++)
            asm volatile("mbarrier.init.shared.b64 [%0], %1;" :: "r"(mb + 8 * s), "r"(1u) : "memory");
        asm volatile("fence.proxy.async.shared::cta;" ::: "memory");
    }
    __syncthreads();

#define ISSUE(c, s)                                                              \
    do {                                                                         \
        if (tid == 0) {                                                          \
            uint32_t mb_ = mb + 8 * (s);                                         \
            mbar_expect(mb_, STAGE_B);                                           \
            uint32_t st_ = base + (s) * STAGE_B;                                 \
            bulk_cp(st_, (const char*)Ah + (mtC + (c)) * A_TILE_B, A_TILE_B, mb_); \
            bulk_cp(st_ + A_TILE_B, (const char*)Bh + (ntC + (c)) * B_TILE_B, B_TILE_B, mb_); \
        }                                                                        \
    } while (0)

#pragma unroll
    for (int p = 0; p < NSTAGE - 1; p++) ISSUE(p, p);

    // per-thread ldsm address components (swizzled 64B rows)
    const int rowA = wm * 64 + (lane & 15);
    const int xa = (rowA >> 1) & 3;
    const int lsA = lane >> 4;
    const uint32_t cA0 = (uint32_t)((lsA ^ xa) << 4);
    const uint32_t cA1 = (uint32_t)(((2 | lsA) ^ xa) << 4);
    const uint32_t aRow = (uint32_t)rowA * 64;

    const int rowB = wn * 64 + (lane & 7) + ((lane & 16) >> 1);
    const int xb = (rowB >> 1) & 3;
    const int lsB = (lane & 8) >> 3;
    const uint32_t cB0 = (uint32_t)((lsB ^ xb) << 4);
    const uint32_t cB1 = (uint32_t)(((2 | lsB) ^ xb) << 4);
    const uint32_t bRow = (uint32_t)rowB * 64;

    float c[4][8][4];
#pragma unroll
    for (int mi = 0; mi < 4; mi++)
#pragma unroll
        for (int ni = 0; ni < 8; ni++)
#pragma unroll
            for (int j = 0; j < 4; j++) c[mi][ni][j] = 0.f;

    for (int ck = 0; ck < CHUNKS; ck++) {
        const int s = ck & 7;
        mbar_wait(mb + 8 * s, (ck >> 3) & 1);

        const uint32_t sb = base + s * STAGE_B;
        const uint32_t aHi = sb + aRow;
        const uint32_t bHi = sb + A_TILE_B + bRow;

#pragma unroll
        for (int kk = 0; kk < 2; kk++) {
            const uint32_t ca = kk ? cA1 : cA0;
            const uint32_t cb = kk ? cB1 : cB0;
            uint32_t bh[16];
#pragma unroll
            for (int g = 0; g < 4; g++) ldsm4(bh + g * 4, bHi + g * 1024 + cb);
#pragma unroll
            for (int mi = 0; mi < 4; mi++) {
                uint32_t ah[4];
                ldsm4(ah, aHi + mi * 1024 + ca);
#pragma unroll
                for (int ni = 0; ni < 8; ni++)
                    mma_f16(c[mi][ni], ah, &bh[ni * 2]);
            }
        }
        __syncthreads();
        if (ck + NSTAGE - 1 < CHUNKS) ISSUE(ck + NSTAGE - 1, (ck + NSTAGE - 1) & 7);
    }

    // epilogue: route by nt>>5 (fused QKV), col block = (nt & 31) * 128
    float* Cb = (nt < 32) ? C0 : (nt < 64) ? C1 : C2;
    float* Cw = Cb + (size_t)(mt * 256 + wm * 64) * DIM + (nt & 31) * 128 + wn * 64;
    const int cr = lane >> 2, cc = (lane & 3) * 2;
#pragma unroll
    for (int mi = 0; mi < 4; mi++)
#pragma unroll
        for (int ni = 0; ni < 8; ni++) {
            float* p0 = Cw + (size_t)(mi * 16 + cr) * DIM + ni * 8 + cc;
            float* p1 = p0 + 8 * DIM;
            *(float2*)p0 = make_float2(c[mi][ni][0], c[mi][ni][1]);
            *(float2*)p1 = make_float2(c[mi][ni][2], c[mi][ni][3]);
        }
}

// ---------------------------------------------------------------------------
// Rotary + bf16 split for Q (scaled by log2e/sqrt(d)) and K. (unchanged)
// ---------------------------------------------------------------------------
__global__ __launch_bounds__(256) void rotary_convert(
        const float* __restrict__ Q, float* __restrict__ Kf,
        const float* __restrict__ fc,
        __nv_bfloat16* __restrict__ qh, __nv_bfloat16* __restrict__ ql,
        __nv_bfloat16* __restrict__ kh, __nv_bfloat16* __restrict__ kl) {
    const float QSC = 1.44269504088896f / 11.3137084989848f;
    int idx = blockIdx.x * blockDim.x + threadIdx.x;
    int p = idx & 63;
    int h = (idx >> 6) & 31;
    int s = (idx >> 11) & (SEQLEN - 1);
    int b = idx >> 22;

    float c = fc[(s * 64 + p) * 2];
    float sn = fc[(s * 64 + p) * 2 + 1];

    size_t in = (((size_t)(b * SEQLEN + s) * NHEADS) + h) * HDIM + p * 2;
    size_t out = (((size_t)(b * NHEADS + h) * SEQLEN) + s) * HDIM + p * 2;

    float2 q = *(float2*)(Q + in);
    float2 k = *(float2*)(Kf + in);
    float2 qo = {q.x * c - q.y * sn, q.x * sn + q.y * c};
    float2 ko = {k.x * c - k.y * sn, k.x * sn + k.y * c};
    *(float2*)(Kf + in) = ko;

    uint32_t hi, lo;
    split2(qo.x * QSC, qo.y * QSC, hi, lo);
    *(uint32_t*)(qh + out) = hi;
    *(uint32_t*)(ql + out) = lo;
    split2(ko.x, ko.y, hi, lo);
    *(uint32_t*)(kh + out) = hi;
    *(uint32_t*)(kl + out) = lo;
}

// ---------------------------------------------------------------------------
// V transpose + split (unchanged)
// ---------------------------------------------------------------------------
__global__ __launch_bounds__(256) void v_transpose(const float* __restrict__ V,
                                                   __nv_bfloat16* __restrict__ vth,
                                                   __nv_bfloat16* __restrict__ vtl) {
    __shared__ float t[32][33];
    int s0 = blockIdx.x * 32, d0 = blockIdx.y * 32;
    int bh = blockIdx.z;
    int b = bh >> 5, h = bh & 31;
#pragma unroll
    for (int i = 0; i < 4; i++) {
        int s = s0 + threadIdx.y + i * 8;
        t[threadIdx.y + i * 8][threadIdx.x] =
            V[(((size_t)(b * SEQLEN + s) * NHEADS) + h) * HDIM + d0 + threadIdx.x];
    }
    __syncthreads();
#pragma unroll
    for (int i = 0; i < 4; i++) {
        int d = d0 + threadIdx.y + i * 8;
        float v = t[threadIdx.x][threadIdx.y + i * 8];
        __nv_bfloat16 hb = __float2bfloat16(v);
        size_t o = ((size_t)bh * HDIM + d) * SEQLEN + s0 + threadIdx.x;
        vth[o] = hb;
        vtl[o] = __float2bfloat16(v - __bfloat162float(hb));
    }
}

// ---------------------------------------------------------------------------
// Flash attention, split-bf16 mma.sync (math unchanged). Epilogue writes
// fp16 (hi only) in the 256-row tiled A layout for the Wo GEMM.
// ---------------------------------------------------------------------------
__global__ __launch_bounds__(256)
void flash_attn(const __nv_bfloat16* __restrict__ Qh, const __nv_bfloat16* __restrict__ Ql,
                const __nv_bfloat16* __restrict__ Kbh, const __nv_bfloat16* __restrict__ Kbl,
                const __nv_bfloat16* __restrict__ Vth, const __nv_bfloat16* __restrict__ Vtl,
                __half* __restrict__ Oh) {
    extern __shared__ char sm_raw[];
    const uint32_t base = smem_u32(sm_raw);
    const int tid = threadIdx.x, warp = tid >> 5, lane = tid & 31;
    const int qt = blockIdx.x, h = blockIdx.y, b = blockIdx.z;
    const size_t bhd = (size_t)(b * NHEADS + h);

    const uint32_t sQh = base, sQl = base + Q_BYTES;
    const uint32_t sKV = base + 2 * Q_BYTES;

    {
        const char* gq = (const char*)(Qh + (bhd * SEQLEN + qt * 128) * HDIM);
        const char* gl = (const char*)(Ql + (bhd * SEQLEN + qt * 128) * HDIM);
        int row = tid >> 4, ch = tid & 15;
#pragma unroll
        for (int i = 0; i < 8; i++) {
            int r = row + i * 16;
            cp16(sQh + r * AQ_STRIDE + ch * 16, gq + r * 256 + ch * 16);
            cp16(sQl + r * AQ_STRIDE + ch * 16, gl + r * 256 + ch * 16);
        }
    }

#define LOADKV(kb_, p_)                                                              \
    do {                                                                             \
        uint32_t kvb_ = sKV + (p_) * KVBUF_BYTES;                                    \
        const char* gkh_ = (const char*)(Kbh + (bhd * SEQLEN + (kb_) * 64) * HDIM);  \
        const char* gkl_ = (const char*)(Kbl + (bhd * SEQLEN + (kb_) * 64) * HDIM);  \
        {                                                                            \
            int row_ = tid >> 4, ch_ = tid & 15;                                     \
            _Pragma("unroll")                                                        \
            for (int i_ = 0; i_ < 4; i_++) {                                         \
                int r_ = row_ + i_ * 16;                                             \
                cp16(kvb_ + r_ * AQ_STRIDE + ch_ * 16, gkh_ + r_ * 256 + ch_ * 16);  \
                cp16(kvb_ + K_BYTES + r_ * AQ_STRIDE + ch_ * 16,                     \
                     gkl_ + r_ * 256 + ch_ * 16);                                    \
            }                                                                        \
        }                                                                            \
        const char* gvh_ = (const char*)(Vth + bhd * HDIM * SEQLEN + (kb_) * 64);    \
        const char* gvl_ = (const char*)(Vtl + bhd * HDIM * SEQLEN + (kb_) * 64);    \
        {                                                                            \
            int row_ = tid >> 3, ch_ = tid & 7;                                      \
            _Pragma("unroll")                                                        \
            for (int i_ = 0; i_ < 4; i_++) {                                         \
                int r_ = row_ + i_ * 32;                                             \
                cp16(kvb_ + 2 * K_BYTES + r_ * AV_STRIDE + ch_ * 16,                 \
                     gvh_ + (size_t)r_ * SEQLEN * 2 + ch_ * 16);                     \
                cp16(kvb_ + 2 * K_BYTES + VT_BYTES + r_ * AV_STRIDE + ch_ * 16,      \
                     gvl_ + (size_t)r_ * SEQLEN * 2 + ch_ * 16);                     \
            }                                                                        \
        }                                                                            \
        asm volatile("cp.async.commit_group;" ::: "memory");                         \
    } while (0)

    const int nt = 2 * qt + 2;
    LOADKV(0, 0);
    LOADKV(1, 1);

    const uint32_t aQoff = (warp * 16 + (lane & 15)) * AQ_STRIDE + ((lane >> 4) << 4);
    const uint32_t bKoff = ((lane & 7) + ((lane & 16) >> 1)) * AQ_STRIDE + (lane & 8) * 2;
    const uint32_t bVoff = ((lane & 7) + ((lane & 16) >> 1)) * AV_STRIDE + (lane & 8) * 2;

    float o[16][4];
#pragma unroll
    for (int j = 0; j < 16; j++)
#pragma unroll
        for (int c = 0; c < 4; c++) o[j][c] = 0.f;
    float m_run[2] = {-1e30f, -1e30f}, l_run[2] = {0.f, 0.f};

    for (int kb = 0; kb < nt; kb++) {
        const uint32_t kvb = sKV + (kb & 1) * KVBUF_BYTES;
        if (kb + 1 < nt) asm volatile("cp.async.wait_group 1;" ::: "memory");
        else             asm volatile("cp.async.wait_group 0;" ::: "memory");
        __syncthreads();

        float s[8][4];
#pragma unroll
        for (int j = 0; j < 8; j++)
#pragma unroll
            for (int c = 0; c < 4; c++) s[j][c] = 0.f;

#pragma unroll
        for (int ks = 0; ks < 8; ks++) {
            uint32_t ah[4], al[4];
            ldsm4(ah, sQh + aQoff + ks * 32);
            ldsm4(al, sQl + aQoff + ks * 32);
#pragma unroll
            for (int nb = 0; nb < 4; nb++) {
                uint32_t kh4[4], kl4[4];
                ldsm4(kh4, kvb + bKoff + nb * 16 * AQ_STRIDE + ks * 32);
                ldsm4(kl4, kvb + K_BYTES + bKoff + nb * 16 * AQ_STRIDE + ks * 32);
                mma16816(s[nb * 2], ah, kh4);
                mma16816(s[nb * 2], al, kh4);
                mma16816(s[nb * 2], ah, kl4);
                mma16816(s[nb * 2 + 1], ah, kh4 + 2);
                mma16816(s[nb * 2 + 1], al, kh4 + 2);
                mma16816(s[nb * 2 + 1], ah, kl4 + 2);
            }
        }

        if (kb >= 2 * qt) {
            int r0 = qt * 128 + warp * 16 + (lane >> 2);
            int c0 = kb * 64 + (lane & 3) * 2;
#pragma unroll
            for (int j = 0; j < 8; j++)
#pragma unroll
                for (int c = 0; c < 4; c++) {
                    int col = c0 + j * 8 + (c & 1);
                    int row = r0 + ((c & 2) ? 8 : 0);
                    if (col > row) s[j][c] = -1e30f;
                }
        }

        float mloc[2] = {-1e30f, -1e30f};
#pragma unroll
        for (int j = 0; j < 8; j++) {
            mloc[0] = fmaxf(mloc[0], fmaxf(s[j][0], s[j][1]));
            mloc[1] = fmaxf(mloc[1], fmaxf(s[j][2], s[j][3]));
        }
        float mnew[2], alpha[2], rs[2];
#pragma unroll
        for (int h2 = 0; h2 < 2; h2++) {
            mloc[h2] = fmaxf(mloc[h2], __shfl_xor_sync(0xffffffffu, mloc[h2], 1));
            mloc[h2] = fmaxf(mloc[h2], __shfl_xor_sync(0xffffffffu, mloc[h2], 2));
            mnew[h2] = fmaxf(m_run[h2], mloc[h2]);
            alpha[h2] = exp2f(m_run[h2] - mnew[h2]);
            rs[h2] = 0.f;
        }
#pragma unroll
        for (int j = 0; j < 8; j++) {
            s[j][0] = exp2f(s[j][0] - mnew[0]);
            s[j][1] = exp2f(s[j][1] - mnew[0]);
            s[j][2] = exp2f(s[j][2] - mnew[1]);
            s[j][3] = exp2f(s[j][3] - mnew[1]);
            rs[0] += s[j][0] + s[j][1];
            rs[1] += s[j][2] + s[j][3];
        }
#pragma unroll
        for (int h2 = 0; h2 < 2; h2++) {
            rs[h2] += __shfl_xor_sync(0xffffffffu, rs[h2], 1);
            rs[h2] += __shfl_xor_sync(0xffffffffu, rs[h2], 2);
            l_run[h2] = l_run[h2] * alpha[h2] + rs[h2];
            m_run[h2] = mnew[h2];
        }
#pragma unroll
        for (int j = 0; j < 16; j++) {
            o[j][0] *= alpha[0];
            o[j][1] *= alpha[0];
            o[j][2] *= alpha[1];
            o[j][3] *= alpha[1];
        }

#pragma unroll
        for (int kc = 0; kc < 4; kc++) {
            uint32_t pah[4], pal[4];
            split2(s[2 * kc][0], s[2 * kc][1], pah[0], pal[0]);
            split2(s[2 * kc][2], s[2 * kc][3], pah[1], pal[1]);
            split2(s[2 * kc + 1][0], s[2 * kc + 1][1], pah[2], pal[2]);
            split2(s[2 * kc + 1][2], s[2 * kc + 1][3], pah[3], pal[3]);
#pragma unroll
            for (int nb = 0; nb < 8; nb++) {
                uint32_t vh4[4], vl4[4];
                ldsm4(vh4, kvb + 2 * K_BYTES + bVoff + nb * 16 * AV_STRIDE + kc * 32);
                ldsm4(vl4, kvb + 2 * K_BYTES + VT_BYTES + bVoff + nb * 16 * AV_STRIDE + kc * 32);
                mma16816(o[nb * 2], pah, vh4);
                mma16816(o[nb * 2], pal, vh4);
                mma16816(o[nb * 2], pah, vl4);
                mma16816(o[nb * 2 + 1], pah, vh4 + 2);
                mma16816(o[nb * 2 + 1], pal, vh4 + 2);
                mma16816(o[nb * 2 + 1], pah, vl4 + 2);
            }
        }

        if (kb + 2 < nt) {
            __syncthreads();
            LOADKV(kb + 2, kb & 1);
        }
    }

    // normalize + write fp16 (hi only) in 256-row tiled-A layout for Wo GEMM
    float inv[2] = {1.f / l_run[0], 1.f / l_run[1]};
    int trow = b * SEQLEN + qt * 128 + warp * 16 + (lane >> 2);
#pragma unroll
    for (int j = 0; j < 16; j++) {
        int c0 = j * 8 + (lane & 3) * 2;
        int k = h * HDIM + c0;
        int ck = k >> 5, c16 = (k & 31) >> 3, bo = (k & 7) * 2;
#pragma unroll
        for (int h2 = 0; h2 < 2; h2++) {
            int t = trow + h2 * 8;
            int mtA = t >> 8, rr = t & 255;
            size_t off = ((((size_t)(mtA * 128 + ck)) * 256 + rr) << 6) +
                         ((c16 ^ ((rr >> 1) & 3)) << 4) + bo;
            __half2 hv = __floats2half2_rn(o[j][h2 * 2] * inv[h2],
                                           o[j][h2 * 2 + 1] * inv[h2]);
            *(uint32_t*)((char*)Oh + off) = *(uint32_t*)&hv;
        }
    }
}

// ---------------------------------------------------------------------------
extern "C" void kernel_launch(void* const* d_in, const int* in_sizes, int n_in,
                              void* d_out, int out_size) {
    const float* x  = (const float*)d_in[0];
    const float* fc = (const float*)d_in[1];
    const float* wq = (const float*)d_in[4];
    const float* wk = (const float*)d_in[5];
    const float* wv = (const float*)d_in[6];
    const float* wo = (const float*)d_in[7];

    float* out = (float*)d_out;
    float* Kh = out + OUT_ELEMS;
    float* Vh = Kh + OUT_ELEMS;

    float* qbuf;
    __half *xh, *wh, *ah;
    __nv_bfloat16 *qh, *ql, *kbh, *kbl, *vth, *vtl;
    cudaGetSymbolAddress((void**)&qbuf, g_Q);
    cudaGetSymbolAddress((void**)&xh, g_xh);
    cudaGetSymbolAddress((void**)&wh, g_wh);
    cudaGetSymbolAddress((void**)&ah, g_ah);
    cudaGetSymbolAddress((void**)&qh, g_qh);
    cudaGetSymbolAddress((void**)&ql, g_ql);
    cudaGetSymbolAddress((void**)&kbh, g_kh);
    cudaGetSymbolAddress((void**)&kbl, g_kl);
    cudaGetSymbolAddress((void**)&vth, g_vth);
    cudaGetSymbolAddress((void**)&vtl, g_vtl);

    const int cblocks = (int)(WSZ / 8 / 256);   // 8 elems per thread

    convert_A<<<cblocks, 256>>>(x, xh);
    convert_W<<<dim3(cblocks, 4), 256>>>(wq, wk, wv, wo, wh);

    cudaFuncSetAttribute(gemm_f16, cudaFuncAttributeMaxDynamicSharedMemorySize, GEMM_SMEM);

    // Fused QKV projection (B tiles 0..95 span wq, wk, wv)
    gemm_f16<<<dim3(96, NTOK / 256), 256, GEMM_SMEM>>>(xh, wh, qbuf, Kh, Vh);

    int rtotal = BSZ * SEQLEN * NHEADS * (HDIM / 2);
    rotary_convert<<<rtotal / 256, 256>>>(qbuf, Kh, fc, qh, ql, kbh, kbl);
    v_transpose<<<dim3(SEQLEN / 32, HDIM / 32, BSZ * NHEADS), dim3(32, 8)>>>(Vh, vth, vtl);

    cudaFuncSetAttribute(flash_attn, cudaFuncAttributeMaxDynamicSharedMemorySize, ATTN_SMEM);
    flash_attn<<<dim3(SEQLEN / 128, NHEADS, BSZ), 256, ATTN_SMEM>>>(
        qh, ql, kbh, kbl, vth, vtl, ah);

    // Output projection (A = attention output in tiled layout)
    gemm_f16<<<dim3(32, NTOK / 256), 256, GEMM_SMEM>>>(
        ah, wh + 3 * WSZ, out, out, out);
}

// round 11
// speedup vs baseline: 6.9822x; 1.2095x over previous
#include <cuda_runtime.h>
#include <cuda_bf16.h>
#include <cuda_fp16.h>
#include <cstdint>

#define BSZ 2
#define SEQLEN 2048
#define NHEADS 32
#define HDIM 128
#define DIM 4096
#define NTOK (BSZ * SEQLEN)              // 4096
#define OUT_ELEMS ((size_t)NTOK * DIM)   // 16,777,216
#define WSZ ((size_t)DIM * DIM)

// ---------------- GEMM tiling: 256x128 CTA tile, BK=32, 1-term fp16 ---------
#define BK 32
#define CHUNKS (DIM / BK)                // 128
#define A_TILE_B 16384                   // 256 rows x 64 B
#define B_TILE_B 8192                    // 128 rows x 64 B
#define STAGE_B (A_TILE_B + B_TILE_B)    // 24576
#define NSTAGE 8
#define GEMM_SMEM (NSTAGE * STAGE_B + 64)       // 196672 B

// ---------------- attention tiling: 1-term fp16 ----------------
#define AQ_STRIDE 272                    // bytes per Q/K smem row (136 halves)
#define AV_STRIDE 144                    // bytes per Vt smem row (72 halves)
#define Q_BYTES (128 * AQ_STRIDE)        // 34816
#define K_BYTES (64 * AQ_STRIDE)         // 17408
#define VT_BYTES (128 * AV_STRIDE)       // 18432
#define KVBUF_BYTES (K_BYTES + VT_BYTES)           // 35840
#define ATTN_SMEM (Q_BYTES + 2 * KVBUF_BYTES)      // 106496

// ---------------- scratch (device globals; no allocation allowed) -----------
__device__ __align__(256) float g_Q[OUT_ELEMS];
__device__ __align__(256) __half g_xh[OUT_ELEMS];       // x fp16 (A layout)
__device__ __align__(256) __half g_wh[4ull * WSZ];      // weights fp16 (B layout)
__device__ __align__(256) __half g_ah[OUT_ELEMS];       // attn out fp16 (A layout)
__device__ __align__(256) __half g_q16[OUT_ELEMS];      // rotated Q fp16 [B,H,S,D]
__device__ __align__(256) __half g_k16[OUT_ELEMS];      // rotated K fp16 [B,H,S,D]
__device__ __align__(256) __half g_vt16[OUT_ELEMS];     // V^T fp16 [B,H,D,S]

// ---------------- PTX helpers ------------------------------------------------
__device__ __forceinline__ uint32_t smem_u32(const void* p) {
    uint32_t a;
    asm("{ .reg .u64 t; cvta.to.shared.u64 t, %1; cvt.u32.u64 %0, t; }" : "=r"(a) : "l"(p));
    return a;
}
__device__ __forceinline__ void cp16(uint32_t dst, const void* src) {
    asm volatile("cp.async.cg.shared.global [%0], [%1], 16;" :: "r"(dst), "l"(src));
}
__device__ __forceinline__ void bulk_cp(uint32_t dst, const void* src, uint32_t bytes,
                                        uint32_t mbar) {
    asm volatile(
        "cp.async.bulk.shared::cta.global.mbarrier::complete_tx::bytes [%0], [%1], %2, [%3];"
        :: "r"(dst), "l"(src), "r"(bytes), "r"(mbar) : "memory");
}
__device__ __forceinline__ void mbar_expect(uint32_t mbar, uint32_t bytes) {
    asm volatile("mbarrier.arrive.expect_tx.shared.b64 _, [%0], %1;"
                 :: "r"(mbar), "r"(bytes) : "memory");
}
__device__ __forceinline__ void mbar_wait(uint32_t mbar, uint32_t parity) {
    asm volatile(
        "{\n\t.reg .pred P;\n\t"
        "LAB%=:\n\t"
        "mbarrier.try_wait.parity.acquire.cta.shared::cta.b64 P, [%0], %1, 0x989680;\n\t"
        "@!P bra LAB%=;\n\t}"
        :: "r"(mbar), "r"(parity) : "memory");
}
__device__ __forceinline__ void ldsm4(uint32_t* r, uint32_t addr) {
    asm volatile("ldmatrix.sync.aligned.m8n8.x4.shared.b16 {%0,%1,%2,%3}, [%4];"
        : "=r"(r[0]), "=r"(r[1]), "=r"(r[2]), "=r"(r[3]) : "r"(addr));
}
__device__ __forceinline__ void mma_f16(float* c, const uint32_t* a, const uint32_t* b) {
    asm volatile("mma.sync.aligned.m16n8k16.row.col.f32.f16.f16.f32 "
        "{%0,%1,%2,%3}, {%4,%5,%6,%7}, {%8,%9}, {%0,%1,%2,%3};"
        : "+f"(c[0]), "+f"(c[1]), "+f"(c[2]), "+f"(c[3])
        : "r"(a[0]), "r"(a[1]), "r"(a[2]), "r"(a[3]), "r"(b[0]), "r"(b[1]));
}

// ---------------------------------------------------------------------------
// x (fp32) -> fp16, A layout (256-row tiles):
// off = ((mt*128+ck)*256 + rr)*64 + (c16 ^ ((rr>>1)&3))*16
// ---------------------------------------------------------------------------
__global__ __launch_bounds__(256) void convert_A(const float* __restrict__ src,
                                                 __half* __restrict__ hi) {
    int idx = blockIdx.x * 256 + threadIdx.x;
    int r = idx >> 9;
    int k = (idx & 511) << 3;
    const float4* s = (const float4*)(src + ((size_t)r << 12) + k);
    float4 v0 = s[0], v1 = s[1];
    float f[8] = {v0.x, v0.y, v0.z, v0.w, v1.x, v1.y, v1.z, v1.w};
    __half h8[8];
#pragma unroll
    for (int j = 0; j < 8; j++) h8[j] = __float2half_rn(f[j]);
    int mt = r >> 8, rr = r & 255, ck = k >> 5, c16 = (k & 31) >> 3;
    size_t off = ((((size_t)(mt * 128 + ck)) * 256 + rr) << 6) +
                 ((c16 ^ ((rr >> 1) & 3)) << 4);
    *(uint4*)((char*)hi + off) = *(uint4*)h8;
}

// ---------------------------------------------------------------------------
// weights (fp32) -> fp16, B layout (128-row tiles). blockIdx.y = matrix.
// ---------------------------------------------------------------------------
__global__ __launch_bounds__(256) void convert_W(
        const float* __restrict__ w0, const float* __restrict__ w1,
        const float* __restrict__ w2, const float* __restrict__ w3,
        __half* __restrict__ out) {
    int m = blockIdx.y;
    const float* src = (m == 0) ? w0 : (m == 1) ? w1 : (m == 2) ? w2 : w3;
    __half* hi = out + (size_t)m * WSZ;

    int idx = blockIdx.x * 256 + threadIdx.x;
    int r = idx >> 9;
    int k = (idx & 511) << 3;
    const float4* s = (const float4*)(src + ((size_t)r << 12) + k);
    float4 v0 = s[0], v1 = s[1];
    float f[8] = {v0.x, v0.y, v0.z, v0.w, v1.x, v1.y, v1.z, v1.w};
    __half h8[8];
#pragma unroll
    for (int j = 0; j < 8; j++) h8[j] = __float2half_rn(f[j]);
    int nt = r >> 7, rr = r & 127, ck = k >> 5, c16 = (k & 31) >> 3;
    size_t off = ((((size_t)(nt * 128 + ck)) * 128 + rr) << 6) +
                 ((c16 ^ ((rr >> 1) & 3)) << 4);
    *(uint4*)((char*)hi + off) = *(uint4*)h8;
}

// ---------------------------------------------------------------------------
// fp16 1-term GEMM (unchanged from round 10).
// ---------------------------------------------------------------------------
__global__ __launch_bounds__(256)
void gemm_f16(const __half* __restrict__ Ah, const __half* __restrict__ Bh,
              float* __restrict__ C0, float* __restrict__ C1, float* __restrict__ C2) {
    extern __shared__ char sm_raw[];
    const uint32_t base = smem_u32(sm_raw);
    const uint32_t mb = base + NSTAGE * STAGE_B;
    const int tid = threadIdx.x;
    const int warp = tid >> 5, lane = tid & 31;
    const int wm = warp & 3, wn = warp >> 2;
    const int nt = blockIdx.x, mt = blockIdx.y;
    const size_t mtC = (size_t)mt * CHUNKS;
    const size_t ntC = (size_t)nt * CHUNKS;

    if (tid == 0) {
#pragma unroll
        for (int s = 0; s < NSTAGE; s++)
            asm volatile("mbarrier.init.shared.b64 [%0], %1;" :: "r"(mb + 8 * s), "r"(1u) : "memory");
        asm volatile("fence.proxy.async.shared::cta;" ::: "memory");
    }
    __syncthreads();

#define ISSUE(c, s)                                                              \
    do {                                                                         \
        if (tid == 0) {                                                          \
            uint32_t mb_ = mb + 8 * (s);                                         \
            mbar_expect(mb_, STAGE_B);                                           \
            uint32_t st_ = base + (s) * STAGE_B;                                 \
            bulk_cp(st_, (const char*)Ah + (mtC + (c)) * A_TILE_B, A_TILE_B, mb_); \
            bulk_cp(st_ + A_TILE_B, (const char*)Bh + (ntC + (c)) * B_TILE_B, B_TILE_B, mb_); \
        }                                                                        \
    } while (0)

#pragma unroll
    for (int p = 0; p < NSTAGE - 1; p++) ISSUE(p, p);

    const int rowA = wm * 64 + (lane & 15);
    const int xa = (rowA >> 1) & 3;
    const int lsA = lane >> 4;
    const uint32_t cA0 = (uint32_t)((lsA ^ xa) << 4);
    const uint32_t cA1 = (uint32_t)(((2 | lsA) ^ xa) << 4);
    const uint32_t aRow = (uint32_t)rowA * 64;

    const int rowB = wn * 64 + (lane & 7) + ((lane & 16) >> 1);
    const int xb = (rowB >> 1) & 3;
    const int lsB = (lane & 8) >> 3;
    const uint32_t cB0 = (uint32_t)((lsB ^ xb) << 4);
    const uint32_t cB1 = (uint32_t)(((2 | lsB) ^ xb) << 4);
    const uint32_t bRow = (uint32_t)rowB * 64;

    float c[4][8][4];
#pragma unroll
    for (int mi = 0; mi < 4; mi++)
#pragma unroll
        for (int ni = 0; ni < 8; ni++)
#pragma unroll
            for (int j = 0; j < 4; j++) c[mi][ni][j] = 0.f;

    for (int ck = 0; ck < CHUNKS; ck++) {
        const int s = ck & 7;
        mbar_wait(mb + 8 * s, (ck >> 3) & 1);

        const uint32_t sb = base + s * STAGE_B;
        const uint32_t aHi = sb + aRow;
        const uint32_t bHi = sb + A_TILE_B + bRow;

#pragma unroll
        for (int kk = 0; kk < 2; kk++) {
            const uint32_t ca = kk ? cA1 : cA0;
            const uint32_t cb = kk ? cB1 : cB0;
            uint32_t bh[16];
#pragma unroll
            for (int g = 0; g < 4; g++) ldsm4(bh + g * 4, bHi + g * 1024 + cb);
#pragma unroll
            for (int mi = 0; mi < 4; mi++) {
                uint32_t ah[4];
                ldsm4(ah, aHi + mi * 1024 + ca);
#pragma unroll
                for (int ni = 0; ni < 8; ni++)
                    mma_f16(c[mi][ni], ah, &bh[ni * 2]);
            }
        }
        __syncthreads();
        if (ck + NSTAGE - 1 < CHUNKS) ISSUE(ck + NSTAGE - 1, (ck + NSTAGE - 1) & 7);
    }

    float* Cb = (nt < 32) ? C0 : (nt < 64) ? C1 : C2;
    float* Cw = Cb + (size_t)(mt * 256 + wm * 64) * DIM + (nt & 31) * 128 + wn * 64;
    const int cr = lane >> 2, cc = (lane & 3) * 2;
#pragma unroll
    for (int mi = 0; mi < 4; mi++)
#pragma unroll
        for (int ni = 0; ni < 8; ni++) {
            float* p0 = Cw + (size_t)(mi * 16 + cr) * DIM + ni * 8 + cc;
            float* p1 = p0 + 8 * DIM;
            *(float2*)p0 = make_float2(c[mi][ni][0], c[mi][ni][1]);
            *(float2*)p1 = make_float2(c[mi][ni][2], c[mi][ni][3]);
        }
}

// ---------------------------------------------------------------------------
// Rotary: Q (scaled by log2e/sqrt(d)) and K -> fp16 [B,H,S,D]; K fp32 in place.
// ---------------------------------------------------------------------------
__global__ __launch_bounds__(256) void rotary_convert(
        const float* __restrict__ Q, float* __restrict__ Kf,
        const float* __restrict__ fc,
        __half* __restrict__ q16, __half* __restrict__ k16) {
    const float QSC = 1.44269504088896f / 11.3137084989848f;
    int idx = blockIdx.x * blockDim.x + threadIdx.x;
    int p = idx & 63;
    int h = (idx >> 6) & 31;
    int s = (idx >> 11) & (SEQLEN - 1);
    int b = idx >> 22;

    float c = fc[(s * 64 + p) * 2];
    float sn = fc[(s * 64 + p) * 2 + 1];

    size_t in = (((size_t)(b * SEQLEN + s) * NHEADS) + h) * HDIM + p * 2;
    size_t out = (((size_t)(b * NHEADS + h) * SEQLEN) + s) * HDIM + p * 2;

    float2 q = *(float2*)(Q + in);
    float2 k = *(float2*)(Kf + in);
    float2 qo = {q.x * c - q.y * sn, q.x * sn + q.y * c};
    float2 ko = {k.x * c - k.y * sn, k.x * sn + k.y * c};
    *(float2*)(Kf + in) = ko;

    __half2 q2 = __floats2half2_rn(qo.x * QSC, qo.y * QSC);
    __half2 k2 = __floats2half2_rn(ko.x, ko.y);
    *(uint32_t*)(q16 + out) = *(uint32_t*)&q2;
    *(uint32_t*)(k16 + out) = *(uint32_t*)&k2;
}

// ---------------------------------------------------------------------------
// V transpose: fp32 [B,S,H,D] -> fp16 [B,H,D,S]
// ---------------------------------------------------------------------------
__global__ __launch_bounds__(256) void v_transpose(const float* __restrict__ V,
                                                   __half* __restrict__ vt16) {
    __shared__ float t[32][33];
    int s0 = blockIdx.x * 32, d0 = blockIdx.y * 32;
    int bh = blockIdx.z;
    int b = bh >> 5, h = bh & 31;
#pragma unroll
    for (int i = 0; i < 4; i++) {
        int s = s0 + threadIdx.y + i * 8;
        t[threadIdx.y + i * 8][threadIdx.x] =
            V[(((size_t)(b * SEQLEN + s) * NHEADS) + h) * HDIM + d0 + threadIdx.x];
    }
    __syncthreads();
#pragma unroll
    for (int i = 0; i < 4; i++) {
        int d = d0 + threadIdx.y + i * 8;
        float v = t[threadIdx.x][threadIdx.y + i * 8];
        size_t o = ((size_t)bh * HDIM + d) * SEQLEN + s0 + threadIdx.x;
        vt16[o] = __float2half_rn(v);
    }
}

// ---------------------------------------------------------------------------
// Flash attention, 1-term fp16 mma.sync. CTA: 128 q-rows x (head, batch).
// 8 warps, warp owns 16 q-rows. K-tile 64, double-buffered cp.async.
// Epilogue writes fp16 in 256-row tiled-A layout for the Wo GEMM.
// ---------------------------------------------------------------------------
__global__ __launch_bounds__(256)
void flash_attn(const __half* __restrict__ Q16,
                const __half* __restrict__ K16,
                const __half* __restrict__ Vt16,
                __half* __restrict__ Oh) {
    extern __shared__ char sm_raw[];
    const uint32_t base = smem_u32(sm_raw);
    const int tid = threadIdx.x, warp = tid >> 5, lane = tid & 31;
    const int qt = blockIdx.x, h = blockIdx.y, b = blockIdx.z;
    const size_t bhd = (size_t)(b * NHEADS + h);

    const uint32_t sQ = base;
    const uint32_t sKV = base + Q_BYTES;

    {
        const char* gq = (const char*)(Q16 + (bhd * SEQLEN + qt * 128) * HDIM);
        int row = tid >> 4, ch = tid & 15;
#pragma unroll
        for (int i = 0; i < 8; i++) {
            int r = row + i * 16;
            cp16(sQ + r * AQ_STRIDE + ch * 16, gq + r * 256 + ch * 16);
        }
    }

#define LOADKV(kb_, p_)                                                              \
    do {                                                                             \
        uint32_t kvb_ = sKV + (p_) * KVBUF_BYTES;                                    \
        const char* gk_ = (const char*)(K16 + (bhd * SEQLEN + (kb_) * 64) * HDIM);   \
        {                                                                            \
            int row_ = tid >> 4, ch_ = tid & 15;                                     \
            _Pragma("unroll")                                                        \
            for (int i_ = 0; i_ < 4; i_++) {                                         \
                int r_ = row_ + i_ * 16;                                             \
                cp16(kvb_ + r_ * AQ_STRIDE + ch_ * 16, gk_ + r_ * 256 + ch_ * 16);   \
            }                                                                        \
        }                                                                            \
        const char* gv_ = (const char*)(Vt16 + bhd * HDIM * SEQLEN + (kb_) * 64);    \
        {                                                                            \
            int row_ = tid >> 3, ch_ = tid & 7;                                      \
            _Pragma("unroll")                                                        \
            for (int i_ = 0; i_ < 4; i_++) {                                         \
                int r_ = row_ + i_ * 32;                                             \
                cp16(kvb_ + K_BYTES + r_ * AV_STRIDE + ch_ * 16,                     \
                     gv_ + (size_t)r_ * SEQLEN * 2 + ch_ * 16);                      \
            }                                                                        \
        }                                                                            \
        asm volatile("cp.async.commit_group;" ::: "memory");                         \
    } while (0)

    const int nt = 2 * qt + 2;
    LOADKV(0, 0);
    LOADKV(1, 1);

    const uint32_t aQoff = (warp * 16 + (lane & 15)) * AQ_STRIDE + ((lane >> 4) << 4);
    const uint32_t bKoff = ((lane & 7) + ((lane & 16) >> 1)) * AQ_STRIDE + (lane & 8) * 2;
    const uint32_t bVoff = ((lane & 7) + ((lane & 16) >> 1)) * AV_STRIDE + (lane & 8) * 2;

    float o[16][4];
#pragma unroll
    for (int j = 0; j < 16; j++)
#pragma unroll
        for (int c = 0; c < 4; c++) o[j][c] = 0.f;
    float m_run[2] = {-1e30f, -1e30f}, l_run[2] = {0.f, 0.f};

    for (int kb = 0; kb < nt; kb++) {
        const uint32_t kvb = sKV + (kb & 1) * KVBUF_BYTES;
        if (kb + 1 < nt) asm volatile("cp.async.wait_group 1;" ::: "memory");
        else             asm volatile("cp.async.wait_group 0;" ::: "memory");
        __syncthreads();

        // ---- S = Q @ K^T (1 fp16 term) ----
        float s[8][4];
#pragma unroll
        for (int j = 0; j < 8; j++)
#pragma unroll
            for (int c = 0; c < 4; c++) s[j][c] = 0.f;

#pragma unroll
        for (int ks = 0; ks < 8; ks++) {
            uint32_t ah[4];
            ldsm4(ah, sQ + aQoff + ks * 32);
#pragma unroll
            for (int nb = 0; nb < 4; nb++) {
                uint32_t kh4[4];
                ldsm4(kh4, kvb + bKoff + nb * 16 * AQ_STRIDE + ks * 32);
                mma_f16(s[nb * 2], ah, kh4);
                mma_f16(s[nb * 2 + 1], ah, kh4 + 2);
            }
        }

        if (kb >= 2 * qt) {
            int r0 = qt * 128 + warp * 16 + (lane >> 2);
            int c0 = kb * 64 + (lane & 3) * 2;
#pragma unroll
            for (int j = 0; j < 8; j++)
#pragma unroll
                for (int c = 0; c < 4; c++) {
                    int col = c0 + j * 8 + (c & 1);
                    int row = r0 + ((c & 2) ? 8 : 0);
                    if (col > row) s[j][c] = -1e30f;
                }
        }

        float mloc[2] = {-1e30f, -1e30f};
#pragma unroll
        for (int j = 0; j < 8; j++) {
            mloc[0] = fmaxf(mloc[0], fmaxf(s[j][0], s[j][1]));
            mloc[1] = fmaxf(mloc[1], fmaxf(s[j][2], s[j][3]));
        }
        float mnew[2], alpha[2], rs[2];
#pragma unroll
        for (int h2 = 0; h2 < 2; h2++) {
            mloc[h2] = fmaxf(mloc[h2], __shfl_xor_sync(0xffffffffu, mloc[h2], 1));
            mloc[h2] = fmaxf(mloc[h2], __shfl_xor_sync(0xffffffffu, mloc[h2], 2));
            mnew[h2] = fmaxf(m_run[h2], mloc[h2]);
            alpha[h2] = exp2f(m_run[h2] - mnew[h2]);
            rs[h2] = 0.f;
        }
#pragma unroll
        for (int j = 0; j < 8; j++) {
            s[j][0] = exp2f(s[j][0] - mnew[0]);
            s[j][1] = exp2f(s[j][1] - mnew[0]);
            s[j][2] = exp2f(s[j][2] - mnew[1]);
            s[j][3] = exp2f(s[j][3] - mnew[1]);
            rs[0] += s[j][0] + s[j][1];
            rs[1] += s[j][2] + s[j][3];
        }
#pragma unroll
        for (int h2 = 0; h2 < 2; h2++) {
            rs[h2] += __shfl_xor_sync(0xffffffffu, rs[h2], 1);
            rs[h2] += __shfl_xor_sync(0xffffffffu, rs[h2], 2);
            l_run[h2] = l_run[h2] * alpha[h2] + rs[h2];
            m_run[h2] = mnew[h2];
        }
#pragma unroll
        for (int j = 0; j < 16; j++) {
            o[j][0] *= alpha[0];
            o[j][1] *= alpha[0];
            o[j][2] *= alpha[1];
            o[j][3] *= alpha[1];
        }

        // ---- O += P @ V (1 fp16 term) ----
#pragma unroll
        for (int kc = 0; kc < 4; kc++) {
            uint32_t pa[4];
            __half2 p0 = __floats2half2_rn(s[2 * kc][0], s[2 * kc][1]);
            __half2 p1 = __floats2half2_rn(s[2 * kc][2], s[2 * kc][3]);
            __half2 p2 = __floats2half2_rn(s[2 * kc + 1][0], s[2 * kc + 1][1]);
            __half2 p3 = __floats2half2_rn(s[2 * kc + 1][2], s[2 * kc + 1][3]);
            pa[0] = *(uint32_t*)&p0;
            pa[1] = *(uint32_t*)&p1;
            pa[2] = *(uint32_t*)&p2;
            pa[3] = *(uint32_t*)&p3;
#pragma unroll
            for (int nb = 0; nb < 8; nb++) {
                uint32_t vh4[4];
                ldsm4(vh4, kvb + K_BYTES + bVoff + nb * 16 * AV_STRIDE + kc * 32);
                mma_f16(o[nb * 2], pa, vh4);
                mma_f16(o[nb * 2 + 1], pa, vh4 + 2);
            }
        }

        if (kb + 2 < nt) {
            __syncthreads();
            LOADKV(kb + 2, kb & 1);
        }
    }

    // normalize + write fp16 in 256-row tiled-A layout for Wo GEMM
    float inv[2] = {1.f / l_run[0], 1.f / l_run[1]};
    int trow = b * SEQLEN + qt * 128 + warp * 16 + (lane >> 2);
#pragma unroll
    for (int j = 0; j < 16; j++) {
        int c0 = j * 8 + (lane & 3) * 2;
        int k = h * HDIM + c0;
        int ck = k >> 5, c16 = (k & 31) >> 3, bo = (k & 7) * 2;
#pragma unroll
        for (int h2 = 0; h2 < 2; h2++) {
            int t = trow + h2 * 8;
            int mtA = t >> 8, rr = t & 255;
            size_t off = ((((size_t)(mtA * 128 + ck)) * 256 + rr) << 6) +
                         ((c16 ^ ((rr >> 1) & 3)) << 4) + bo;
            __half2 hv = __floats2half2_rn(o[j][h2 * 2] * inv[h2],
                                           o[j][h2 * 2 + 1] * inv[h2]);
            *(uint32_t*)((char*)Oh + off) = *(uint32_t*)&hv;
        }
    }
}

// ---------------------------------------------------------------------------
extern "C" void kernel_launch(void* const* d_in, const int* in_sizes, int n_in,
                              void* d_out, int out_size) {
    const float* x  = (const float*)d_in[0];
    const float* fc = (const float*)d_in[1];
    const float* wq = (const float*)d_in[4];
    const float* wk = (const float*)d_in[5];
    const float* wv = (const float*)d_in[6];
    const float* wo = (const float*)d_in[7];

    float* out = (float*)d_out;
    float* Kh = out + OUT_ELEMS;
    float* Vh = Kh + OUT_ELEMS;

    float* qbuf;
    __half *xh, *wh, *ah, *q16, *k16, *vt16;
    cudaGetSymbolAddress((void**)&qbuf, g_Q);
    cudaGetSymbolAddress((void**)&xh, g_xh);
    cudaGetSymbolAddress((void**)&wh, g_wh);
    cudaGetSymbolAddress((void**)&ah, g_ah);
    cudaGetSymbolAddress((void**)&q16, g_q16);
    cudaGetSymbolAddress((void**)&k16, g_k16);
    cudaGetSymbolAddress((void**)&vt16, g_vt16);

    const int cblocks = (int)(WSZ / 8 / 256);   // 8 elems per thread

    convert_A<<<cblocks, 256>>>(x, xh);
    convert_W<<<dim3(cblocks, 4), 256>>>(wq, wk, wv, wo, wh);

    cudaFuncSetAttribute(gemm_f16, cudaFuncAttributeMaxDynamicSharedMemorySize, GEMM_SMEM);

    // Fused QKV projection (B tiles 0..95 span wq, wk, wv)
    gemm_f16<<<dim3(96, NTOK / 256), 256, GEMM_SMEM>>>(xh, wh, qbuf, Kh, Vh);

    int rtotal = BSZ * SEQLEN * NHEADS * (HDIM / 2);
    rotary_convert<<<rtotal / 256, 256>>>(qbuf, Kh, fc, q16, k16);
    v_transpose<<<dim3(SEQLEN / 32, HDIM / 32, BSZ * NHEADS), dim3(32, 8)>>>(Vh, vt16);

    cudaFuncSetAttribute(flash_attn, cudaFuncAttributeMaxDynamicSharedMemorySize, ATTN_SMEM);
    flash_attn<<<dim3(SEQLEN / 128, NHEADS, BSZ), 256, ATTN_SMEM>>>(q16, k16, vt16, ah);

    // Output projection (A = attention output in tiled layout)
    gemm_f16<<<dim3(32, NTOK / 256), 256, GEMM_SMEM>>>(
        ah, wh + 3 * WSZ, out, out, out);
}